// round 15
// baseline (speedup 1.0000x reference)
#include <cuda_runtime.h>
#include <cuda_fp16.h>
#include <math.h>
#include <stdint.h>

#define TT     2048
#define HHD    2048
#define NHEADS 16
#define HDIM   128
#define QSZ    2048
#define KVSZ   512
#define QKVN   3072
#define NEXP   8
#define II     4096
#define EPSV   1e-5f

// ---------------- device scratch ----------------
__device__ __align__(256) float g_xn  [TT * HHD];
__device__ __align__(256) float g_qkv [TT * QKVN];
__device__ __align__(256) float g_att [TT * QSZ];
__device__ __align__(256) float g_x2  [TT * HHD];
__device__ __align__(256) float g_y   [TT * HHD];
__device__ __align__(256) float g_y16 [TT * HHD / 2];
__device__ __align__(256) float g_g   [TT * II / 2];
__device__ int   g_expert[TT];
__device__ float g_gate  [TT];
__device__ int   g_cnt[NEXP];
__device__ int   g_off[NEXP];
__device__ int   g_cur[NEXP];
__device__ int   g_perm[TT];
__device__ __align__(256) float g_wqkvT [QKVN * HHD / 2];
__device__ __align__(256) float g_wqkvTl[QKVN * HHD / 2];
__device__ __align__(256) float g_woT   [HHD * QSZ / 2];
__device__ __align__(256) float g_woTl  [HHD * QSZ / 2];
__device__ __align__(256) float g_wsgT  [II * HHD / 2];
__device__ __align__(256) float g_wsuT  [II * HHD / 2];
__device__ __align__(256) float g_wsdT  [HHD * II / 2];
__device__ __align__(256) float g_wegT  [NEXP * II * HHD / 2];
__device__ __align__(256) float g_weuT  [NEXP * II * HHD / 2];
__device__ __align__(256) float g_wedT  [NEXP * HHD * II / 2];

#define LOSCALE 1024.0f
#define INVLOSCALE (1.0f / 1024.0f)

// ---------------- helpers ----------------
__device__ __forceinline__ uint32_t smem_u32(const void* p) {
    uint32_t a;
    asm("{ .reg .u64 t; cvta.to.shared.u64 t, %1; cvt.u32.u64 %0, t; }" : "=r"(a) : "l"(p));
    return a;
}
__device__ __forceinline__ uint32_t packh2(float a, float b) {
    __half2 h = __floats2half2_rn(a, b);
    return *(uint32_t*)&h;
}
__device__ __forceinline__ void cpa16(uint32_t dst, const void* src) {
    asm volatile("cp.async.cg.shared.global [%0], [%1], 16;" :: "r"(dst), "l"(src) : "memory");
}
#define CP_COMMIT() asm volatile("cp.async.commit_group;" ::: "memory")
#define CP_WAIT1()  asm volatile("cp.async.wait_group 1;" ::: "memory")
#define CP_WAIT0()  asm volatile("cp.async.wait_group 0;" ::: "memory")

#define MMA_F16(d, a, b0, b1) \
  asm volatile("mma.sync.aligned.m16n8k16.row.col.f32.f16.f16.f32 " \
    "{%0,%1,%2,%3}, {%4,%5,%6,%7}, {%8,%9}, {%0,%1,%2,%3};" \
    : "+f"((d)[0]), "+f"((d)[1]), "+f"((d)[2]), "+f"((d)[3]) \
    : "r"((a)[0]), "r"((a)[1]), "r"((a)[2]), "r"((a)[3]), "r"(b0), "r"(b1))

// ---------------- transposes (stride-65 smem) ----------------
__global__ __launch_bounds__(256) void transpose_f16(
    const float* __restrict__ in, __half* __restrict__ out, int R, int C)
{
    __shared__ float t[64 * 65];
    in  += (size_t)blockIdx.z * (size_t)R * C;
    out += (size_t)blockIdx.z * (size_t)R * C;
    int c0 = blockIdx.x * 64, r0 = blockIdx.y * 64;
#pragma unroll
    for (int it = 0; it < 4; it++) {
        int idx = threadIdx.x + 256 * it;
        int r = idx >> 4, cq = (idx & 15) << 2;
        float4 v = *(const float4*)&in[(size_t)(r0 + r) * C + c0 + cq];
        t[(cq + 0) * 65 + r] = v.x;
        t[(cq + 1) * 65 + r] = v.y;
        t[(cq + 2) * 65 + r] = v.z;
        t[(cq + 3) * 65 + r] = v.w;
    }
    __syncthreads();
#pragma unroll
    for (int it = 0; it < 4; it++) {
        int idx = threadIdx.x + 256 * it;
        int c = idx >> 4, q = (idx & 15) << 2;
        uint2 v;
        v.x = packh2(t[c * 65 + q + 0], t[c * 65 + q + 1]);
        v.y = packh2(t[c * 65 + q + 2], t[c * 65 + q + 3]);
        *(uint2*)&out[(size_t)(c0 + c) * R + r0 + q] = v;
    }
}

__global__ __launch_bounds__(256) void transpose_split_h(
    const float* __restrict__ in, __half* __restrict__ hi, __half* __restrict__ lo,
    int R, int C)
{
    __shared__ float t[64 * 65];
    int c0 = blockIdx.x * 64, r0 = blockIdx.y * 64;
#pragma unroll
    for (int it = 0; it < 4; it++) {
        int idx = threadIdx.x + 256 * it;
        int r = idx >> 4, cq = (idx & 15) << 2;
        float4 v = *(const float4*)&in[(size_t)(r0 + r) * C + c0 + cq];
        t[(cq + 0) * 65 + r] = v.x;
        t[(cq + 1) * 65 + r] = v.y;
        t[(cq + 2) * 65 + r] = v.z;
        t[(cq + 3) * 65 + r] = v.w;
    }
    __syncthreads();
#pragma unroll
    for (int it = 0; it < 4; it++) {
        int idx = threadIdx.x + 256 * it;
        int c = idx >> 4, q = (idx & 15) << 2;
        float x0 = t[c * 65 + q + 0], x1 = t[c * 65 + q + 1];
        float x2 = t[c * 65 + q + 2], x3 = t[c * 65 + q + 3];
        float h0 = __half2float(__float2half_rn(x0));
        float h1 = __half2float(__float2half_rn(x1));
        float h2 = __half2float(__float2half_rn(x2));
        float h3 = __half2float(__float2half_rn(x3));
        uint2 vh, vl;
        vh.x = packh2(x0, x1);
        vh.y = packh2(x2, x3);
        vl.x = packh2((x0 - h0) * LOSCALE, (x1 - h1) * LOSCALE);
        vl.y = packh2((x2 - h2) * LOSCALE, (x3 - h3) * LOSCALE);
        size_t o = (size_t)(c0 + c) * R + r0 + q;
        *(uint2*)&hi[o] = vh;
        *(uint2*)&lo[o] = vl;
    }
}

// ---------------- fp16 GEMM (plain, fp16 A): 2-stage all-cp.async (R13-proven) ----------------
#define HSTR 20
#define HTILE (128 * HSTR)
#define HSTG  (2 * HTILE)
#define SMEM_H (2 * HSTG * 4)

template<int MODE>
__global__ void __launch_bounds__(256) gemm_h(
    const __half* __restrict__ A, const __half* __restrict__ BT,
    float* __restrict__ C, int M, int N, int K, const float* __restrict__ Res)
{
    int e = blockIdx.z;
    int cnt = M, base = 0;
    if (MODE) {
        cnt = g_cnt[e]; base = g_off[e];
        if ((int)blockIdx.y * 128 >= cnt) return;
        BT += (size_t)e * (size_t)N * K;
    }
    int bm = blockIdx.y * 128, bn = blockIdx.x * 128;
    int tid = threadIdx.x, lane = tid & 31, warp = tid >> 5;
    int wm = warp & 3, wn = warp >> 2;
    int g = lane >> 2, tig = lane & 3;

    extern __shared__ __align__(16) float smf[];
    uint32_t smb = smem_u32(smf);
    const uint32_t* SM = (const uint32_t*)smf;

    const __half* aptr[2]; const __half* bptr[2];
    uint32_t aoff[2], boff[2];
#pragma unroll
    for (int i = 0; i < 2; i++) {
        int idx = tid + 256 * i;
        int r = idx >> 2, cg = idx & 3;
        int row;
        if (MODE == 1) { int rr = bm + r; if (rr >= cnt) rr = cnt - 1; row = g_perm[base + rr]; }
        else if (MODE == 2) { int rr = bm + r; if (rr >= cnt) rr = cnt - 1; row = base + rr; }
        else row = bm + r;
        aptr[i] = A + (size_t)row * K + cg * 8;
        bptr[i] = BT + (size_t)(bn + r) * K + cg * 8;
        aoff[i] = (uint32_t)(r * HSTR + cg * 4) * 4;
        boff[i] = (uint32_t)(HTILE + r * HSTR + cg * 4) * 4;
    }

#pragma unroll
    for (int i = 0; i < 2; i++) {
        cpa16(smb + aoff[i], aptr[i]);
        cpa16(smb + boff[i], bptr[i]);
    }
    CP_COMMIT();

    float acc[2][8][4];
#pragma unroll
    for (int mt = 0; mt < 2; mt++)
#pragma unroll
        for (int nt = 0; nt < 8; nt++)
#pragma unroll
            for (int q = 0; q < 4; q++) acc[mt][nt][q] = 0.f;

    const int abase = (wm * 32 + g) * HSTR + tig;
    const int bbase = (wn * 64 + g) * HSTR + tig;
    const int KC = K / 32;

    for (int c = 0; c < KC; c++) {
        int s = c & 1;
        bool more = (c + 1 < KC);
        if (more) {
            uint32_t nb = smb + (uint32_t)(s ^ 1) * HSTG * 4;
#pragma unroll
            for (int i = 0; i < 2; i++) {
                cpa16(nb + aoff[i], aptr[i] + (c + 1) * 32);
                cpa16(nb + boff[i], bptr[i] + (c + 1) * 32);
            }
            CP_COMMIT();
            CP_WAIT1();
        } else {
            CP_WAIT0();
        }
        __syncthreads();

        const uint32_t* AH = SM + s * HSTG;
        const uint32_t* BH = AH + HTILE;

#pragma unroll
        for (int ks = 0; ks < 2; ks++) {
            uint32_t ah[2][4];
#pragma unroll
            for (int mt = 0; mt < 2; mt++) {
                int a0 = abase + mt * 16 * HSTR + ks * 8;
                ah[mt][0] = AH[a0];
                ah[mt][1] = AH[a0 + 8 * HSTR];
                ah[mt][2] = AH[a0 + 4];
                ah[mt][3] = AH[a0 + 8 * HSTR + 4];
            }
#pragma unroll
            for (int nt = 0; nt < 8; nt++) {
                int b0i = bbase + nt * 8 * HSTR + ks * 8;
                uint32_t b0 = BH[b0i], b1 = BH[b0i + 4];
#pragma unroll
                for (int mt = 0; mt < 2; mt++)
                    MMA_F16(acc[mt][nt], ah[mt], b0, b1);
            }
        }
        __syncthreads();
    }

#pragma unroll
    for (int mt = 0; mt < 2; mt++) {
        int mloc0 = wm * 32 + mt * 16 + g;
#pragma unroll
        for (int nt = 0; nt < 8; nt++) {
            int col = bn + wn * 64 + nt * 8 + 2 * tig;
            float* d = acc[mt][nt];
            if (MODE == 0) {
                size_t i0 = (size_t)(bm + mloc0) * N + col;
                size_t i1 = (size_t)(bm + mloc0 + 8) * N + col;
                float2 v0 = make_float2(d[0], d[1]);
                float2 v1 = make_float2(d[2], d[3]);
                if (Res) {
                    float2 r0 = *(const float2*)&Res[i0];
                    float2 r1 = *(const float2*)&Res[i1];
                    v0.x += r0.x; v0.y += r0.y; v1.x += r1.x; v1.y += r1.y;
                }
                *(float2*)&C[i0] = v0;
                *(float2*)&C[i1] = v1;
            } else {
                if (bm + mloc0 < cnt) {
                    int tok = g_perm[base + bm + mloc0];
                    float gt = g_gate[tok];
                    size_t i0 = (size_t)tok * N + col;
                    float2 o = *(const float2*)&C[i0];
                    o.x += gt * d[0]; o.y += gt * d[1];
                    *(float2*)&C[i0] = o;
                }
                if (bm + mloc0 + 8 < cnt) {
                    int tok = g_perm[base + bm + mloc0 + 8];
                    float gt = g_gate[tok];
                    size_t i1 = (size_t)tok * N + col;
                    float2 o = *(const float2*)&C[i1];
                    o.x += gt * d[2]; o.y += gt * d[3];
                    *(float2*)&C[i1] = o;
                }
            }
        }
    }
}

// ---------------- fused gate+up GEMM, fp16 A, silu -> fp16 C, 2-stage (R13-proven) ----------------
#define GSTG (3 * HTILE)
#define SMEM_GU (2 * GSTG * 4)

template<int MODE>
__global__ void __launch_bounds__(256) gemm_gu(
    const __half* __restrict__ A, const __half* __restrict__ BG,
    const __half* __restrict__ BU, __half* __restrict__ C,
    int M, int N, int K)
{
    int e = blockIdx.z;
    int cnt = M, base = 0;
    if (MODE) {
        cnt = g_cnt[e]; base = g_off[e];
        if ((int)blockIdx.y * 128 >= cnt) return;
        BG += (size_t)e * (size_t)N * K;
        BU += (size_t)e * (size_t)N * K;
    }
    int bm = blockIdx.y * 128, bn = blockIdx.x * 128;
    int tid = threadIdx.x, lane = tid & 31, warp = tid >> 5;
    int wm = warp & 3, wn = warp >> 2;
    int g = lane >> 2, tig = lane & 3;

    extern __shared__ __align__(16) float smf[];
    uint32_t smb = smem_u32(smf);
    const uint32_t* SM = (const uint32_t*)smf;

    const __half* aptr[2]; const __half* bgp[2]; const __half* bup[2];
    uint32_t aoff[2], boff[2];
#pragma unroll
    for (int i = 0; i < 2; i++) {
        int idx = tid + 256 * i;
        int r = idx >> 2, cg = idx & 3;
        int row;
        if (MODE == 1) { int rr = bm + r; if (rr >= cnt) rr = cnt - 1; row = g_perm[base + rr]; }
        else row = bm + r;
        aptr[i] = A + (size_t)row * K + cg * 8;
        bgp[i]  = BG + (size_t)(bn + r) * K + cg * 8;
        bup[i]  = BU + (size_t)(bn + r) * K + cg * 8;
        aoff[i] = (uint32_t)(r * HSTR + cg * 4) * 4;
        boff[i] = (uint32_t)(HTILE + r * HSTR + cg * 4) * 4;
    }

#pragma unroll
    for (int i = 0; i < 2; i++) {
        cpa16(smb + aoff[i], aptr[i]);
        cpa16(smb + boff[i], bgp[i]);
        cpa16(smb + HTILE * 4 + boff[i], bup[i]);
    }
    CP_COMMIT();

    float accg[2][8][4], accu[2][8][4];
#pragma unroll
    for (int mt = 0; mt < 2; mt++)
#pragma unroll
        for (int nt = 0; nt < 8; nt++)
#pragma unroll
            for (int q = 0; q < 4; q++) { accg[mt][nt][q] = 0.f; accu[mt][nt][q] = 0.f; }

    const int abase = (wm * 32 + g) * HSTR + tig;
    const int bbase = (wn * 64 + g) * HSTR + tig;
    const int KC = K / 32;

    for (int c = 0; c < KC; c++) {
        int s = c & 1;
        bool more = (c + 1 < KC);
        if (more) {
            uint32_t nb = smb + (uint32_t)(s ^ 1) * GSTG * 4;
#pragma unroll
            for (int i = 0; i < 2; i++) {
                cpa16(nb + aoff[i], aptr[i] + (c + 1) * 32);
                cpa16(nb + boff[i], bgp[i] + (c + 1) * 32);
                cpa16(nb + HTILE * 4 + boff[i], bup[i] + (c + 1) * 32);
            }
            CP_COMMIT();
            CP_WAIT1();
        } else {
            CP_WAIT0();
        }
        __syncthreads();

        const uint32_t* AH = SM + s * GSTG;
        const uint32_t* BGs = AH + HTILE;
        const uint32_t* BUs = AH + 2 * HTILE;

#pragma unroll
        for (int ks = 0; ks < 2; ks++) {
            uint32_t ah[2][4];
#pragma unroll
            for (int mt = 0; mt < 2; mt++) {
                int a0 = abase + mt * 16 * HSTR + ks * 8;
                ah[mt][0] = AH[a0];
                ah[mt][1] = AH[a0 + 8 * HSTR];
                ah[mt][2] = AH[a0 + 4];
                ah[mt][3] = AH[a0 + 8 * HSTR + 4];
            }
#pragma unroll
            for (int nt = 0; nt < 8; nt++) {
                int b0i = bbase + nt * 8 * HSTR + ks * 8;
                uint32_t bg0 = BGs[b0i], bg1 = BGs[b0i + 4];
                uint32_t bu0 = BUs[b0i], bu1 = BUs[b0i + 4];
#pragma unroll
                for (int mt = 0; mt < 2; mt++) {
                    MMA_F16(accg[mt][nt], ah[mt], bg0, bg1);
                    MMA_F16(accu[mt][nt], ah[mt], bu0, bu1);
                }
            }
        }
        __syncthreads();
    }

#pragma unroll
    for (int mt = 0; mt < 2; mt++) {
        int mloc0 = wm * 32 + mt * 16 + g;
#pragma unroll
        for (int nt = 0; nt < 8; nt++) {
            int col = bn + wn * 64 + nt * 8 + 2 * tig;
            float* dg = accg[mt][nt];
            float* du = accu[mt][nt];
            float h0 = (dg[0] / (1.0f + __expf(-dg[0]))) * du[0];
            float h1 = (dg[1] / (1.0f + __expf(-dg[1]))) * du[1];
            float h2 = (dg[2] / (1.0f + __expf(-dg[2]))) * du[2];
            float h3 = (dg[3] / (1.0f + __expf(-dg[3]))) * du[3];
            uint32_t p0 = packh2(h0, h1);
            uint32_t p1 = packh2(h2, h3);
            if (MODE == 0) {
                size_t i0 = (size_t)(bm + mloc0) * N + col;
                size_t i1 = (size_t)(bm + mloc0 + 8) * N + col;
                *(uint32_t*)&C[i0] = p0;
                *(uint32_t*)&C[i1] = p1;
            } else {
                if (bm + mloc0 < cnt) {
                    size_t i0 = (size_t)(base + bm + mloc0) * N + col;
                    *(uint32_t*)&C[i0] = p0;
                }
                if (bm + mloc0 + 8 < cnt) {
                    size_t i1 = (size_t)(base + bm + mloc0 + 8) * N + col;
                    *(uint32_t*)&C[i1] = p1;
                }
            }
        }
    }
}

// ---------------- double-fp16 compensated GEMM (router-upstream, unchanged) ----------------
#define HCSTG (4 * HTILE)
#define SMEM_HC (2 * HCSTG * 4)

__global__ void __launch_bounds__(256) gemm_hc(
    const float* __restrict__ A, const __half* __restrict__ BHI,
    const __half* __restrict__ BLO, float* __restrict__ C,
    int M, int N, int K, const float* __restrict__ Res)
{
    int bm = blockIdx.y * 128, bn = blockIdx.x * 128;
    int tid = threadIdx.x, lane = tid & 31, warp = tid >> 5;
    int wm = warp & 3, wn = warp >> 2;
    int g = lane >> 2, tig = lane & 3;

    extern __shared__ __align__(16) float smf[];
    uint32_t smb = smem_u32(smf);
    const uint32_t* SM = (const uint32_t*)smf;

    const float* aptr[2]; const __half* bhp[2]; const __half* blp[2];
    uint32_t aoff[2], boff[2];
#pragma unroll
    for (int i = 0; i < 2; i++) {
        int idx = tid + 256 * i;
        int r = idx >> 2, cg = idx & 3;
        aptr[i] = A + (size_t)(bm + r) * K + cg * 8;
        bhp[i]  = BHI + (size_t)(bn + r) * K + cg * 8;
        blp[i]  = BLO + (size_t)(bn + r) * K + cg * 8;
        aoff[i] = (uint32_t)(r * HSTR + cg * 4) * 4;
        boff[i] = (uint32_t)(HTILE + r * HSTR + cg * 4) * 4;
    }

    float4 areg[2][2];
#pragma unroll
    for (int i = 0; i < 2; i++) {
        areg[i][0] = *(const float4*)(aptr[i]);
        areg[i][1] = *(const float4*)(aptr[i] + 4);
        cpa16(smb + boff[i], bhp[i]);
        cpa16(smb + 2 * HTILE * 4 + boff[i], blp[i]);
    }
    CP_COMMIT();
#pragma unroll
    for (int i = 0; i < 2; i++) {
        float x0 = areg[i][0].x, x1 = areg[i][0].y, x2 = areg[i][0].z, x3 = areg[i][0].w;
        float x4 = areg[i][1].x, x5 = areg[i][1].y, x6 = areg[i][1].z, x7 = areg[i][1].w;
        float h0 = __half2float(__float2half_rn(x0)), h1 = __half2float(__float2half_rn(x1));
        float h2 = __half2float(__float2half_rn(x2)), h3 = __half2float(__float2half_rn(x3));
        float h4 = __half2float(__float2half_rn(x4)), h5 = __half2float(__float2half_rn(x5));
        float h6 = __half2float(__float2half_rn(x6)), h7 = __half2float(__float2half_rn(x7));
        uint32_t a0 = packh2(x0, x1), a1 = packh2(x2, x3), a2 = packh2(x4, x5), a3 = packh2(x6, x7);
        uint32_t l0 = packh2((x0 - h0) * LOSCALE, (x1 - h1) * LOSCALE);
        uint32_t l1 = packh2((x2 - h2) * LOSCALE, (x3 - h3) * LOSCALE);
        uint32_t l2 = packh2((x4 - h4) * LOSCALE, (x5 - h5) * LOSCALE);
        uint32_t l3 = packh2((x6 - h6) * LOSCALE, (x7 - h7) * LOSCALE);
        asm volatile("st.shared.v4.b32 [%0], {%1,%2,%3,%4};"
                     :: "r"(smb + aoff[i]), "r"(a0), "r"(a1), "r"(a2), "r"(a3) : "memory");
        asm volatile("st.shared.v4.b32 [%0], {%1,%2,%3,%4};"
                     :: "r"(smb + 2 * HTILE * 4 + aoff[i]), "r"(l0), "r"(l1), "r"(l2), "r"(l3) : "memory");
    }

    float acc1[2][8][4], acc2[2][8][4];
#pragma unroll
    for (int mt = 0; mt < 2; mt++)
#pragma unroll
        for (int nt = 0; nt < 8; nt++)
#pragma unroll
            for (int q = 0; q < 4; q++) { acc1[mt][nt][q] = 0.f; acc2[mt][nt][q] = 0.f; }

    const int abase = (wm * 32 + g) * HSTR + tig;
    const int bbase = (wn * 64 + g) * HSTR + tig;
    const int KC = K / 32;

    for (int c = 0; c < KC; c++) {
        int s = c & 1;
        bool more = (c + 1 < KC);
        if (more) {
            uint32_t nb = smb + (uint32_t)(s ^ 1) * HCSTG * 4;
#pragma unroll
            for (int i = 0; i < 2; i++) {
                areg[i][0] = *(const float4*)(aptr[i] + (c + 1) * 32);
                areg[i][1] = *(const float4*)(aptr[i] + (c + 1) * 32 + 4);
                cpa16(nb + boff[i], bhp[i] + (c + 1) * 32);
                cpa16(nb + 2 * HTILE * 4 + boff[i], blp[i] + (c + 1) * 32);
            }
            CP_COMMIT();
            CP_WAIT1();
        } else {
            CP_WAIT0();
        }
        __syncthreads();

        const uint32_t* AH = SM + s * HCSTG;
        const uint32_t* BH = AH + HTILE;
        const uint32_t* AL = AH + 2 * HTILE;
        const uint32_t* BL = AH + 3 * HTILE;

#pragma unroll
        for (int ks = 0; ks < 2; ks++) {
            uint32_t ah[2][4], al[2][4];
#pragma unroll
            for (int mt = 0; mt < 2; mt++) {
                int a0 = abase + mt * 16 * HSTR + ks * 8;
                ah[mt][0] = AH[a0];            ah[mt][1] = AH[a0 + 8 * HSTR];
                ah[mt][2] = AH[a0 + 4];        ah[mt][3] = AH[a0 + 8 * HSTR + 4];
                al[mt][0] = AL[a0];            al[mt][1] = AL[a0 + 8 * HSTR];
                al[mt][2] = AL[a0 + 4];        al[mt][3] = AL[a0 + 8 * HSTR + 4];
            }
#pragma unroll
            for (int nt = 0; nt < 8; nt++) {
                int b0i = bbase + nt * 8 * HSTR + ks * 8;
                uint32_t b0 = BH[b0i], b1 = BH[b0i + 4];
                uint32_t c0 = BL[b0i], c1 = BL[b0i + 4];
#pragma unroll
                for (int mt = 0; mt < 2; mt++) {
                    MMA_F16(acc1[mt][nt], ah[mt], b0, b1);
                    MMA_F16(acc2[mt][nt], ah[mt], c0, c1);
                    MMA_F16(acc2[mt][nt], al[mt], b0, b1);
                }
            }
        }
        __syncthreads();

        if (more) {
            uint32_t nb = smb + (uint32_t)(s ^ 1) * HCSTG * 4;
#pragma unroll
            for (int i = 0; i < 2; i++) {
                float x0 = areg[i][0].x, x1 = areg[i][0].y, x2 = areg[i][0].z, x3 = areg[i][0].w;
                float x4 = areg[i][1].x, x5 = areg[i][1].y, x6 = areg[i][1].z, x7 = areg[i][1].w;
                float h0 = __half2float(__float2half_rn(x0)), h1 = __half2float(__float2half_rn(x1));
                float h2 = __half2float(__float2half_rn(x2)), h3 = __half2float(__float2half_rn(x3));
                float h4 = __half2float(__float2half_rn(x4)), h5 = __half2float(__float2half_rn(x5));
                float h6 = __half2float(__float2half_rn(x6)), h7 = __half2float(__float2half_rn(x7));
                uint32_t a0 = packh2(x0, x1), a1 = packh2(x2, x3), a2 = packh2(x4, x5), a3 = packh2(x6, x7);
                uint32_t l0 = packh2((x0 - h0) * LOSCALE, (x1 - h1) * LOSCALE);
                uint32_t l1 = packh2((x2 - h2) * LOSCALE, (x3 - h3) * LOSCALE);
                uint32_t l2 = packh2((x4 - h4) * LOSCALE, (x5 - h5) * LOSCALE);
                uint32_t l3 = packh2((x6 - h6) * LOSCALE, (x7 - h7) * LOSCALE);
                asm volatile("st.shared.v4.b32 [%0], {%1,%2,%3,%4};"
                             :: "r"(nb + aoff[i]), "r"(a0), "r"(a1), "r"(a2), "r"(a3) : "memory");
                asm volatile("st.shared.v4.b32 [%0], {%1,%2,%3,%4};"
                             :: "r"(nb + 2 * HTILE * 4 + aoff[i]), "r"(l0), "r"(l1), "r"(l2), "r"(l3) : "memory");
            }
        }
    }

#pragma unroll
    for (int mt = 0; mt < 2; mt++) {
        int mloc0 = wm * 32 + mt * 16 + g;
#pragma unroll
        for (int nt = 0; nt < 8; nt++) {
            int col = bn + wn * 64 + nt * 8 + 2 * tig;
            float* d1 = acc1[mt][nt];
            float* d2 = acc2[mt][nt];
            size_t i0 = (size_t)(bm + mloc0) * N + col;
            size_t i1 = (size_t)(bm + mloc0 + 8) * N + col;
            float2 v0 = make_float2(d1[0] + d2[0] * INVLOSCALE, d1[1] + d2[1] * INVLOSCALE);
            float2 v1 = make_float2(d1[2] + d2[2] * INVLOSCALE, d1[3] + d2[3] * INVLOSCALE);
            if (Res) {
                float2 r0 = *(const float2*)&Res[i0];
                float2 r1 = *(const float2*)&Res[i1];
                v0.x += r0.x; v0.y += r0.y; v1.x += r1.x; v1.y += r1.y;
            }
            *(float2*)&C[i0] = v0;
            *(float2*)&C[i1] = v1;
        }
    }
}

// ---------------- rmsnorm ----------------
__global__ __launch_bounds__(256) void rmsnorm_kernel(
    const float* __restrict__ x, const float* __restrict__ w, float* __restrict__ o)
{
    int t = blockIdx.x, tid = threadIdx.x;
    const float* r = x + (size_t)t * HHD;
    float ss = 0.f;
    for (int j = tid; j < HHD; j += 256) { float v = r[j]; ss += v * v; }
    __shared__ float red[256];
    red[tid] = ss; __syncthreads();
    for (int s = 128; s > 0; s >>= 1) { if (tid < s) red[tid] += red[tid + s]; __syncthreads(); }
    float scale = rsqrtf(red[0] / (float)HHD + EPSV);
    float* out = o + (size_t)t * HHD;
    for (int j = tid; j < HHD; j += 256) out[j] = r[j] * scale * w[j];
}

__global__ __launch_bounds__(256) void rmsnorm_dual(
    const float* __restrict__ x, const float* __restrict__ w,
    float* __restrict__ o32, __half* __restrict__ o16)
{
    int t = blockIdx.x, tid = threadIdx.x;
    const float* r = x + (size_t)t * HHD;
    float ss = 0.f;
    for (int j = tid; j < HHD; j += 256) { float v = r[j]; ss += v * v; }
    __shared__ float red[256];
    red[tid] = ss; __syncthreads();
    for (int s = 128; s > 0; s >>= 1) { if (tid < s) red[tid] += red[tid + s]; __syncthreads(); }
    float scale = rsqrtf(red[0] / (float)HHD + EPSV);
    float* out32 = o32 + (size_t)t * HHD;
    __half* out16 = o16 + (size_t)t * HHD;
    for (int j = tid; j < HHD; j += 256) {
        float v = r[j] * scale * w[j];
        out32[j] = v;
        out16[j] = __float2half_rn(v);
    }
}

// ---------------- rope + q/k rmsnorm ----------------
__global__ __launch_bounds__(256) void ropenorm_kernel(
    float* __restrict__ qkv, const int* __restrict__ pos,
    const float* __restrict__ qw, const float* __restrict__ kw)
{
    int t = blockIdx.x, tid = threadIdx.x;
    float* row = qkv + (size_t)t * QKVN;
    float p = (float)pos[t];
    const float lgt = logf(500000.0f);
    __shared__ float red[256];
    __shared__ float sq, sk;

    float ss = 0.f;
    for (int idx = tid; idx < 1024; idx += 256) {
        int hh = idx >> 6, i = idx & 63;
        float inv = expf(-lgt * (float)i * (1.0f / 64.0f));
        float fr = p * inv, c = cosf(fr), s = sinf(fr);
        float x1 = row[hh * 128 + i], x2 = row[hh * 128 + 64 + i];
        float o1 = x1 * c - x2 * s, o2 = x2 * c + x1 * s;
        row[hh * 128 + i] = o1; row[hh * 128 + 64 + i] = o2;
        ss += o1 * o1 + o2 * o2;
    }
    red[tid] = ss; __syncthreads();
    for (int s2 = 128; s2 > 0; s2 >>= 1) { if (tid < s2) red[tid] += red[tid + s2]; __syncthreads(); }
    if (tid == 0) sq = rsqrtf(red[0] / (float)QSZ + EPSV);
    __syncthreads();

    float ssk = 0.f;
    {
        int hh = tid >> 6, i = tid & 63;
        float inv = expf(-lgt * (float)i * (1.0f / 64.0f));
        float fr = p * inv, c = cosf(fr), s = sinf(fr);
        float* kb = row + QSZ;
        float x1 = kb[hh * 128 + i], x2 = kb[hh * 128 + 64 + i];
        float o1 = x1 * c - x2 * s, o2 = x2 * c + x1 * s;
        kb[hh * 128 + i] = o1; kb[hh * 128 + 64 + i] = o2;
        ssk = o1 * o1 + o2 * o2;
    }
    red[tid] = ssk; __syncthreads();
    for (int s2 = 128; s2 > 0; s2 >>= 1) { if (tid < s2) red[tid] += red[tid + s2]; __syncthreads(); }
    if (tid == 0) sk = rsqrtf(red[0] / (float)KVSZ + EPSV);
    __syncthreads();

    for (int j = tid; j < QSZ; j += 256) row[j] *= sq * qw[j];
    for (int j = tid; j < KVSZ; j += 256) row[QSZ + j] *= sk * kw[j];
}

// ---------------- flash attention (fp32, BM=128 tiles) ----------------
#define QKSTR 132
#define PSTR  68
#define SMEM_ATTN ((128 * QKSTR + 2 * 64 * QKSTR + 128 * PSTR) * 4)

__global__ __launch_bounds__(256) void attn_kernel(
    const float* __restrict__ qkv, float* __restrict__ O)
{
    extern __shared__ float sh[];
    float* Qs = sh;                         // 128 x QKSTR
    float* Ks = sh + 128 * QKSTR;           // 64 x QKSTR
    float* Vs = Ks + 64 * QKSTR;            // 64 x QKSTR
    float* Ps = Vs + 64 * QKSTR;            // 128 x PSTR

    int m0 = ((int)gridDim.x - 1 - (int)blockIdx.x) * 128;   // heavy tiles first
    int h  = blockIdx.y;
    int kvh = h >> 2;
    int tid = threadIdx.x, lane = tid & 31, w = tid >> 5;
    const float scl = 0.08838834764831845f;

    for (int i = tid; i < 4096; i += 256) {
        int r = i >> 5, c = (i & 31) << 2;
        *(float4*)&Qs[r * QKSTR + c] =
            *(const float4*)&qkv[(size_t)(m0 + r) * QKVN + h * HDIM + c];
    }

    float mrow[16], lrow[16], oacc[16][4];
#pragma unroll
    for (int r = 0; r < 16; r++) {
        mrow[r] = -1e30f; lrow[r] = 0.f;
        oacc[r][0] = oacc[r][1] = oacc[r][2] = oacc[r][3] = 0.f;
    }
    int d0 = lane << 2;

    for (int n0 = 0; n0 <= m0 + 64; n0 += 64) {
        __syncthreads();
        for (int i = tid; i < 2048; i += 256) {
            int r = i >> 5, c = (i & 31) << 2;
            *(float4*)&Ks[r * QKSTR + c] =
                *(const float4*)&qkv[(size_t)(n0 + r) * QKVN + QSZ + kvh * HDIM + c];
            *(float4*)&Vs[r * QKSTR + c] =
                *(const float4*)&qkv[(size_t)(n0 + r) * QKVN + QSZ + KVSZ + kvh * HDIM + c];
        }
        __syncthreads();

        // S = Q K^T
        float s0[16], s1[16];
#pragma unroll
        for (int r = 0; r < 16; r++) { s0[r] = 0.f; s1[r] = 0.f; }
#pragma unroll 2
        for (int k = 0; k < 128; k += 4) {
            float4 k0 = *(float4*)&Ks[lane * QKSTR + k];
            float4 k1 = *(float4*)&Ks[(lane + 32) * QKSTR + k];
#pragma unroll
            for (int r = 0; r < 16; r++) {
                float4 q = *(float4*)&Qs[(w * 16 + r) * QKSTR + k];
                s0[r] += q.x * k0.x + q.y * k0.y + q.z * k0.z + q.w * k0.w;
                s1[r] += q.x * k1.x + q.y * k1.y + q.z * k1.z + q.w * k1.w;
            }
        }
        bool diag = (n0 + 63 > m0);
#pragma unroll
        for (int r = 0; r < 16; r++) {
            int grow = m0 + w * 16 + r;
            float v0 = s0[r] * scl, v1 = s1[r] * scl;
            if (diag) {
                if (n0 + lane      > grow) v0 = -1e30f;
                if (n0 + lane + 32 > grow) v1 = -1e30f;
            }
            float tmax = fmaxf(v0, v1);
#pragma unroll
            for (int o = 16; o; o >>= 1) tmax = fmaxf(tmax, __shfl_xor_sync(~0u, tmax, o));
            float nm = fmaxf(mrow[r], tmax);
            float p0 = __expf(v0 - nm), p1 = __expf(v1 - nm);
            float corr = __expf(mrow[r] - nm);
            float psum = p0 + p1;
#pragma unroll
            for (int o = 16; o; o >>= 1) psum += __shfl_xor_sync(~0u, psum, o);
            lrow[r] = lrow[r] * corr + psum;
            mrow[r] = nm;
            oacc[r][0] *= corr; oacc[r][1] *= corr; oacc[r][2] *= corr; oacc[r][3] *= corr;
            Ps[(w * 16 + r) * PSTR + lane]      = p0;
            Ps[(w * 16 + r) * PSTR + lane + 32] = p1;
        }
        __syncwarp();
        // O += P V
#pragma unroll 2
        for (int n = 0; n < 64; n += 4) {
            float4 v0 = *(float4*)&Vs[(n + 0) * QKSTR + d0];
            float4 v1 = *(float4*)&Vs[(n + 1) * QKSTR + d0];
            float4 v2 = *(float4*)&Vs[(n + 2) * QKSTR + d0];
            float4 v3 = *(float4*)&Vs[(n + 3) * QKSTR + d0];
#pragma unroll
            for (int r = 0; r < 16; r++) {
                float4 pv = *(float4*)&Ps[(w * 16 + r) * PSTR + n];
                oacc[r][0] += pv.x * v0.x + pv.y * v1.x + pv.z * v2.x + pv.w * v3.x;
                oacc[r][1] += pv.x * v0.y + pv.y * v1.y + pv.z * v2.y + pv.w * v3.y;
                oacc[r][2] += pv.x * v0.z + pv.y * v1.z + pv.z * v2.z + pv.w * v3.z;
                oacc[r][3] += pv.x * v0.w + pv.y * v1.w + pv.z * v2.w + pv.w * v3.w;
            }
        }
    }
#pragma unroll
    for (int r = 0; r < 16; r++) {
        float inv = 1.0f / lrow[r];
        float4 o = make_float4(oacc[r][0] * inv, oacc[r][1] * inv,
                               oacc[r][2] * inv, oacc[r][3] * inv);
        *(float4*)&O[(size_t)(m0 + w * 16 + r) * QSZ + h * HDIM + d0] = o;
    }
}

// ---------------- router / permutation ----------------
__global__ void zero_kernel()
{
    int i = threadIdx.x;
    if (i < NEXP) { g_cnt[i] = 0; g_cur[i] = 0; }
}

__global__ __launch_bounds__(256) void router_kernel(
    const float* __restrict__ y, const float* __restrict__ rw)
{
    int warp = threadIdx.x >> 5, lane = threadIdx.x & 31;
    int t = blockIdx.x * 8 + warp;
    const float4* xr = (const float4*)(y + (size_t)t * HHD);
    float part[NEXP] = {};
#pragma unroll 4
    for (int it = 0; it < 16; it++) {
        int kq = it * 32 + lane;
        float4 xv = xr[kq];
        const float* r0 = rw + (size_t)(kq * 4) * NEXP;
#pragma unroll
        for (int e = 0; e < NEXP; e++)
            part[e] += xv.x * r0[e] + xv.y * r0[NEXP + e]
                     + xv.z * r0[2 * NEXP + e] + xv.w * r0[3 * NEXP + e];
    }
#pragma unroll
    for (int e = 0; e < NEXP; e++)
#pragma unroll
        for (int o = 16; o; o >>= 1) part[e] += __shfl_xor_sync(~0u, part[e], o);
    if (lane == 0) {
        int am = 0; float mv = part[0];
#pragma unroll
        for (int e = 1; e < NEXP; e++) if (part[e] > mv) { mv = part[e]; am = e; }
        g_expert[t] = am;
        g_gate[t]   = 1.0f / (1.0f + expf(-mv));
        atomicAdd(&g_cnt[am], 1);
    }
}

__global__ void scan_kernel()
{
    int s = 0;
    for (int e = 0; e < NEXP; e++) { g_off[e] = s; s += g_cnt[e]; }
}

__global__ void scatter_kernel()
{
    int t = blockIdx.x * 256 + threadIdx.x;
    if (t >= TT) return;
    int e = g_expert[t];
    int p = atomicAdd(&g_cur[e], 1);
    g_perm[g_off[e] + p] = t;
}

// ---------------- launcher ----------------
extern "C" void kernel_launch(void* const* d_in, const int* in_sizes, int n_in,
                              void* d_out, int out_size)
{
    const int*   positions = (const int*)  d_in[0];
    const float* hidden    = (const float*)d_in[1];
    const float* ln1       = (const float*)d_in[2];
    const float* ln2       = (const float*)d_in[3];
    const float* w_qkv     = (const float*)d_in[4];
    const float* w_o       = (const float*)d_in[5];
    const float* qnw       = (const float*)d_in[6];
    const float* knw       = (const float*)d_in[7];
    const float* rw        = (const float*)d_in[8];
    const float* wsg       = (const float*)d_in[9];
    const float* wsu       = (const float*)d_in[10];
    const float* wsd       = (const float*)d_in[11];
    const float* weg       = (const float*)d_in[12];
    const float* weu       = (const float*)d_in[13];
    const float* wed       = (const float*)d_in[14];
    float* out = (float*)d_out;

    void* p;
    cudaGetSymbolAddress(&p, g_xn);  float* xn  = (float*)p;
    cudaGetSymbolAddress(&p, g_qkv); float* qkv = (float*)p;
    cudaGetSymbolAddress(&p, g_att); float* att = (float*)p;
    cudaGetSymbolAddress(&p, g_x2);  float* x2  = (float*)p;
    cudaGetSymbolAddress(&p, g_y);   float* y   = (float*)p;
    cudaGetSymbolAddress(&p, g_y16); __half* y16 = (__half*)p;
    cudaGetSymbolAddress(&p, g_g);   __half* gg16 = (__half*)p;
    cudaGetSymbolAddress(&p, g_wqkvT);  __half* wqkvT  = (__half*)p;
    cudaGetSymbolAddress(&p, g_wqkvTl); __half* wqkvTl = (__half*)p;
    cudaGetSymbolAddress(&p, g_woT);    __half* woT    = (__half*)p;
    cudaGetSymbolAddress(&p, g_woTl);   __half* woTl   = (__half*)p;
    cudaGetSymbolAddress(&p, g_wsgT);   __half* wsgT   = (__half*)p;
    cudaGetSymbolAddress(&p, g_wsuT);   __half* wsuT   = (__half*)p;
    cudaGetSymbolAddress(&p, g_wsdT);   __half* wsdT   = (__half*)p;
    cudaGetSymbolAddress(&p, g_wegT);   __half* wegT   = (__half*)p;
    cudaGetSymbolAddress(&p, g_weuT);   __half* weuT   = (__half*)p;
    cudaGetSymbolAddress(&p, g_wedT);   __half* wedT   = (__half*)p;

    cudaFuncSetAttribute(attn_kernel, cudaFuncAttributeMaxDynamicSharedMemorySize, SMEM_ATTN);
    cudaFuncSetAttribute(gemm_hc, cudaFuncAttributeMaxDynamicSharedMemorySize, SMEM_HC);
    cudaFuncSetAttribute(gemm_h<0>, cudaFuncAttributeMaxDynamicSharedMemorySize, SMEM_H);
    cudaFuncSetAttribute(gemm_h<2>, cudaFuncAttributeMaxDynamicSharedMemorySize, SMEM_H);
    cudaFuncSetAttribute(gemm_gu<0>, cudaFuncAttributeMaxDynamicSharedMemorySize, SMEM_GU);
    cudaFuncSetAttribute(gemm_gu<1>, cudaFuncAttributeMaxDynamicSharedMemorySize, SMEM_GU);

    // weight prep
    transpose_split_h<<<dim3(QKVN / 64, HHD / 64), 256>>>(w_qkv, wqkvT, wqkvTl, HHD, QKVN);
    transpose_split_h<<<dim3(HHD / 64, QSZ / 64), 256>>>(w_o, woT, woTl, QSZ, HHD);
    transpose_f16<<<dim3(II / 64, HHD / 64), 256>>>(wsg, wsgT, HHD, II);
    transpose_f16<<<dim3(II / 64, HHD / 64), 256>>>(wsu, wsuT, HHD, II);
    transpose_f16<<<dim3(HHD / 64, II / 64), 256>>>(wsd, wsdT, II, HHD);
    transpose_f16<<<dim3(II / 64, HHD / 64, NEXP), 256>>>(weg, wegT, HHD, II);
    transpose_f16<<<dim3(II / 64, HHD / 64, NEXP), 256>>>(weu, weuT, HHD, II);
    transpose_f16<<<dim3(HHD / 64, II / 64, NEXP), 256>>>(wed, wedT, II, HHD);

    // 1. x = rmsnorm(hidden, ln1)
    rmsnorm_kernel<<<TT, 256>>>(hidden, ln1, xn);
    // 2. qkv = x @ w_qkv   (double-fp16 compensated — upstream of router)
    gemm_hc<<<dim3(QKVN / 128, TT / 128), 256, SMEM_HC>>>(xn, wqkvT, wqkvTl, qkv, TT, QKVN, HHD, nullptr);
    // 3. rope + q/k norm
    ropenorm_kernel<<<TT, 256>>>(qkv, positions, qnw, knw);
    // 4. attention (BM=128)
    attn_kernel<<<dim3(TT / 128, NHEADS), 256, SMEM_ATTN>>>(qkv, att);
    // 5. x2 = hidden + attn @ w_o   (compensated)
    gemm_hc<<<dim3(HHD / 128, TT / 128), 256, SMEM_HC>>>(att, woT, woTl, x2, TT, HHD, QSZ, hidden);
    // 6. y = rmsnorm(x2, ln2)  -> fp32 (router) + fp16 (GEMM A)
    rmsnorm_dual<<<TT, 256>>>(x2, ln2, y, y16);
    // 7. router (fp32, warp-per-token)
    zero_kernel<<<1, 32>>>();
    router_kernel<<<TT / 8, 256>>>(y, rw);
    scan_kernel<<<1, 1>>>();
    scatter_kernel<<<TT / 256, 256>>>();
    // 8. shared expert: fused gate+up+silu (fp16 out), then down (+x2 residual)
    gemm_gu<0><<<dim3(II / 128, TT / 128), 256, SMEM_GU>>>(y16, wsgT, wsuT, gg16, TT, II, HHD);
    gemm_h<0><<<dim3(HHD / 128, TT / 128), 256, SMEM_H>>>(gg16, wsdT, out, TT, HHD, II, x2);
    // 9. routed experts: fused grouped gate+up+silu, then grouped scatter-add down
    gemm_gu<1><<<dim3(II / 128, TT / 128, NEXP), 256, SMEM_GU>>>(y16, wegT, weuT, gg16, TT, II, HHD);
    gemm_h<2><<<dim3(HHD / 128, TT / 128, NEXP), 256, SMEM_H>>>(gg16, wedT, out, TT, HHD, II, nullptr);
}

// round 16
// speedup vs baseline: 1.0105x; 1.0105x over previous
#include <cuda_runtime.h>
#include <cuda_fp16.h>
#include <math.h>
#include <stdint.h>

#define TT     2048
#define HHD    2048
#define NHEADS 16
#define HDIM   128
#define QSZ    2048
#define KVSZ   512
#define QKVN   3072
#define NEXP   8
#define II     4096
#define EPSV   1e-5f

// ---------------- device scratch ----------------
__device__ __align__(256) float g_xn  [TT * HHD];
__device__ __align__(256) float g_qkv [TT * QKVN];
__device__ __align__(256) float g_att [TT * QSZ];
__device__ __align__(256) float g_x2  [TT * HHD];
__device__ __align__(256) float g_y   [TT * HHD];
__device__ __align__(256) float g_y16 [TT * HHD / 2];
__device__ __align__(256) float g_g   [TT * II / 2];
__device__ int   g_expert[TT];
__device__ float g_gate  [TT];
__device__ int   g_cnt[NEXP];
__device__ int   g_off[NEXP];
__device__ int   g_cur[NEXP];
__device__ int   g_perm[TT];
__device__ __align__(256) float g_wqkvT [QKVN * HHD / 2];
__device__ __align__(256) float g_wqkvTl[QKVN * HHD / 2];
__device__ __align__(256) float g_woT   [HHD * QSZ / 2];
__device__ __align__(256) float g_woTl  [HHD * QSZ / 2];
__device__ __align__(256) float g_wsgT  [II * HHD / 2];
__device__ __align__(256) float g_wsuT  [II * HHD / 2];
__device__ __align__(256) float g_wsdT  [HHD * II / 2];
__device__ __align__(256) float g_wegT  [NEXP * II * HHD / 2];
__device__ __align__(256) float g_weuT  [NEXP * II * HHD / 2];
__device__ __align__(256) float g_wedT  [NEXP * HHD * II / 2];

#define LOSCALE 1024.0f
#define INVLOSCALE (1.0f / 1024.0f)

// ---------------- helpers ----------------
__device__ __forceinline__ uint32_t smem_u32(const void* p) {
    uint32_t a;
    asm("{ .reg .u64 t; cvta.to.shared.u64 t, %1; cvt.u32.u64 %0, t; }" : "=r"(a) : "l"(p));
    return a;
}
__device__ __forceinline__ uint32_t packh2(float a, float b) {
    __half2 h = __floats2half2_rn(a, b);
    return *(uint32_t*)&h;
}
__device__ __forceinline__ void cpa16(uint32_t dst, const void* src) {
    asm volatile("cp.async.cg.shared.global [%0], [%1], 16;" :: "r"(dst), "l"(src) : "memory");
}
#define CP_COMMIT() asm volatile("cp.async.commit_group;" ::: "memory")
#define CP_WAIT1()  asm volatile("cp.async.wait_group 1;" ::: "memory")
#define CP_WAIT0()  asm volatile("cp.async.wait_group 0;" ::: "memory")

#define MMA_F16(d, a, b0, b1) \
  asm volatile("mma.sync.aligned.m16n8k16.row.col.f32.f16.f16.f32 " \
    "{%0,%1,%2,%3}, {%4,%5,%6,%7}, {%8,%9}, {%0,%1,%2,%3};" \
    : "+f"((d)[0]), "+f"((d)[1]), "+f"((d)[2]), "+f"((d)[3]) \
    : "r"((a)[0]), "r"((a)[1]), "r"((a)[2]), "r"((a)[3]), "r"(b0), "r"(b1))

// ---------------- transposes (stride-65 smem) ----------------
__global__ __launch_bounds__(256) void transpose_f16(
    const float* __restrict__ in, __half* __restrict__ out, int R, int C)
{
    __shared__ float t[64 * 65];
    in  += (size_t)blockIdx.z * (size_t)R * C;
    out += (size_t)blockIdx.z * (size_t)R * C;
    int c0 = blockIdx.x * 64, r0 = blockIdx.y * 64;
#pragma unroll
    for (int it = 0; it < 4; it++) {
        int idx = threadIdx.x + 256 * it;
        int r = idx >> 4, cq = (idx & 15) << 2;
        float4 v = *(const float4*)&in[(size_t)(r0 + r) * C + c0 + cq];
        t[(cq + 0) * 65 + r] = v.x;
        t[(cq + 1) * 65 + r] = v.y;
        t[(cq + 2) * 65 + r] = v.z;
        t[(cq + 3) * 65 + r] = v.w;
    }
    __syncthreads();
#pragma unroll
    for (int it = 0; it < 4; it++) {
        int idx = threadIdx.x + 256 * it;
        int c = idx >> 4, q = (idx & 15) << 2;
        uint2 v;
        v.x = packh2(t[c * 65 + q + 0], t[c * 65 + q + 1]);
        v.y = packh2(t[c * 65 + q + 2], t[c * 65 + q + 3]);
        *(uint2*)&out[(size_t)(c0 + c) * R + r0 + q] = v;
    }
}

__global__ __launch_bounds__(256) void transpose_split_h(
    const float* __restrict__ in, __half* __restrict__ hi, __half* __restrict__ lo,
    int R, int C)
{
    __shared__ float t[64 * 65];
    int c0 = blockIdx.x * 64, r0 = blockIdx.y * 64;
#pragma unroll
    for (int it = 0; it < 4; it++) {
        int idx = threadIdx.x + 256 * it;
        int r = idx >> 4, cq = (idx & 15) << 2;
        float4 v = *(const float4*)&in[(size_t)(r0 + r) * C + c0 + cq];
        t[(cq + 0) * 65 + r] = v.x;
        t[(cq + 1) * 65 + r] = v.y;
        t[(cq + 2) * 65 + r] = v.z;
        t[(cq + 3) * 65 + r] = v.w;
    }
    __syncthreads();
#pragma unroll
    for (int it = 0; it < 4; it++) {
        int idx = threadIdx.x + 256 * it;
        int c = idx >> 4, q = (idx & 15) << 2;
        float x0 = t[c * 65 + q + 0], x1 = t[c * 65 + q + 1];
        float x2 = t[c * 65 + q + 2], x3 = t[c * 65 + q + 3];
        float h0 = __half2float(__float2half_rn(x0));
        float h1 = __half2float(__float2half_rn(x1));
        float h2 = __half2float(__float2half_rn(x2));
        float h3 = __half2float(__float2half_rn(x3));
        uint2 vh, vl;
        vh.x = packh2(x0, x1);
        vh.y = packh2(x2, x3);
        vl.x = packh2((x0 - h0) * LOSCALE, (x1 - h1) * LOSCALE);
        vl.y = packh2((x2 - h2) * LOSCALE, (x3 - h3) * LOSCALE);
        size_t o = (size_t)(c0 + c) * R + r0 + q;
        *(uint2*)&hi[o] = vh;
        *(uint2*)&lo[o] = vl;
    }
}

// ---------------- fp16 GEMM (plain, fp16 A): 2-stage all-cp.async (R13-proven) ----------------
#define HSTR 20
#define HTILE (128 * HSTR)
#define HSTG  (2 * HTILE)
#define SMEM_H (2 * HSTG * 4)

template<int MODE>
__global__ void __launch_bounds__(256) gemm_h(
    const __half* __restrict__ A, const __half* __restrict__ BT,
    float* __restrict__ C, int M, int N, int K, const float* __restrict__ Res)
{
    int e = blockIdx.z;
    int cnt = M, base = 0;
    if (MODE) {
        cnt = g_cnt[e]; base = g_off[e];
        if ((int)blockIdx.y * 128 >= cnt) return;
        BT += (size_t)e * (size_t)N * K;
    }
    int bm = blockIdx.y * 128, bn = blockIdx.x * 128;
    int tid = threadIdx.x, lane = tid & 31, warp = tid >> 5;
    int wm = warp & 3, wn = warp >> 2;
    int g = lane >> 2, tig = lane & 3;

    extern __shared__ __align__(16) float smf[];
    uint32_t smb = smem_u32(smf);
    const uint32_t* SM = (const uint32_t*)smf;

    const __half* aptr[2]; const __half* bptr[2];
    uint32_t aoff[2], boff[2];
#pragma unroll
    for (int i = 0; i < 2; i++) {
        int idx = tid + 256 * i;
        int r = idx >> 2, cg = idx & 3;
        int row;
        if (MODE == 1) { int rr = bm + r; if (rr >= cnt) rr = cnt - 1; row = g_perm[base + rr]; }
        else if (MODE == 2) { int rr = bm + r; if (rr >= cnt) rr = cnt - 1; row = base + rr; }
        else row = bm + r;
        aptr[i] = A + (size_t)row * K + cg * 8;
        bptr[i] = BT + (size_t)(bn + r) * K + cg * 8;
        aoff[i] = (uint32_t)(r * HSTR + cg * 4) * 4;
        boff[i] = (uint32_t)(HTILE + r * HSTR + cg * 4) * 4;
    }

#pragma unroll
    for (int i = 0; i < 2; i++) {
        cpa16(smb + aoff[i], aptr[i]);
        cpa16(smb + boff[i], bptr[i]);
    }
    CP_COMMIT();

    float acc[2][8][4];
#pragma unroll
    for (int mt = 0; mt < 2; mt++)
#pragma unroll
        for (int nt = 0; nt < 8; nt++)
#pragma unroll
            for (int q = 0; q < 4; q++) acc[mt][nt][q] = 0.f;

    const int abase = (wm * 32 + g) * HSTR + tig;
    const int bbase = (wn * 64 + g) * HSTR + tig;
    const int KC = K / 32;

    for (int c = 0; c < KC; c++) {
        int s = c & 1;
        bool more = (c + 1 < KC);
        if (more) {
            uint32_t nb = smb + (uint32_t)(s ^ 1) * HSTG * 4;
#pragma unroll
            for (int i = 0; i < 2; i++) {
                cpa16(nb + aoff[i], aptr[i] + (c + 1) * 32);
                cpa16(nb + boff[i], bptr[i] + (c + 1) * 32);
            }
            CP_COMMIT();
            CP_WAIT1();
        } else {
            CP_WAIT0();
        }
        __syncthreads();

        const uint32_t* AH = SM + s * HSTG;
        const uint32_t* BH = AH + HTILE;

#pragma unroll
        for (int ks = 0; ks < 2; ks++) {
            uint32_t ah[2][4];
#pragma unroll
            for (int mt = 0; mt < 2; mt++) {
                int a0 = abase + mt * 16 * HSTR + ks * 8;
                ah[mt][0] = AH[a0];
                ah[mt][1] = AH[a0 + 8 * HSTR];
                ah[mt][2] = AH[a0 + 4];
                ah[mt][3] = AH[a0 + 8 * HSTR + 4];
            }
#pragma unroll
            for (int nt = 0; nt < 8; nt++) {
                int b0i = bbase + nt * 8 * HSTR + ks * 8;
                uint32_t b0 = BH[b0i], b1 = BH[b0i + 4];
#pragma unroll
                for (int mt = 0; mt < 2; mt++)
                    MMA_F16(acc[mt][nt], ah[mt], b0, b1);
            }
        }
        __syncthreads();
    }

#pragma unroll
    for (int mt = 0; mt < 2; mt++) {
        int mloc0 = wm * 32 + mt * 16 + g;
#pragma unroll
        for (int nt = 0; nt < 8; nt++) {
            int col = bn + wn * 64 + nt * 8 + 2 * tig;
            float* d = acc[mt][nt];
            if (MODE == 0) {
                size_t i0 = (size_t)(bm + mloc0) * N + col;
                size_t i1 = (size_t)(bm + mloc0 + 8) * N + col;
                float2 v0 = make_float2(d[0], d[1]);
                float2 v1 = make_float2(d[2], d[3]);
                if (Res) {
                    float2 r0 = *(const float2*)&Res[i0];
                    float2 r1 = *(const float2*)&Res[i1];
                    v0.x += r0.x; v0.y += r0.y; v1.x += r1.x; v1.y += r1.y;
                }
                *(float2*)&C[i0] = v0;
                *(float2*)&C[i1] = v1;
            } else {
                if (bm + mloc0 < cnt) {
                    int tok = g_perm[base + bm + mloc0];
                    float gt = g_gate[tok];
                    size_t i0 = (size_t)tok * N + col;
                    float2 o = *(const float2*)&C[i0];
                    o.x += gt * d[0]; o.y += gt * d[1];
                    *(float2*)&C[i0] = o;
                }
                if (bm + mloc0 + 8 < cnt) {
                    int tok = g_perm[base + bm + mloc0 + 8];
                    float gt = g_gate[tok];
                    size_t i1 = (size_t)tok * N + col;
                    float2 o = *(const float2*)&C[i1];
                    o.x += gt * d[2]; o.y += gt * d[3];
                    *(float2*)&C[i1] = o;
                }
            }
        }
    }
}

// ---------------- fused gate+up GEMM, fp16 A, silu -> fp16 C, 2-stage (R13-proven) ----------------
#define GSTG (3 * HTILE)
#define SMEM_GU (2 * GSTG * 4)

template<int MODE>
__global__ void __launch_bounds__(256) gemm_gu(
    const __half* __restrict__ A, const __half* __restrict__ BG,
    const __half* __restrict__ BU, __half* __restrict__ C,
    int M, int N, int K)
{
    int e = blockIdx.z;
    int cnt = M, base = 0;
    if (MODE) {
        cnt = g_cnt[e]; base = g_off[e];
        if ((int)blockIdx.y * 128 >= cnt) return;
        BG += (size_t)e * (size_t)N * K;
        BU += (size_t)e * (size_t)N * K;
    }
    int bm = blockIdx.y * 128, bn = blockIdx.x * 128;
    int tid = threadIdx.x, lane = tid & 31, warp = tid >> 5;
    int wm = warp & 3, wn = warp >> 2;
    int g = lane >> 2, tig = lane & 3;

    extern __shared__ __align__(16) float smf[];
    uint32_t smb = smem_u32(smf);
    const uint32_t* SM = (const uint32_t*)smf;

    const __half* aptr[2]; const __half* bgp[2]; const __half* bup[2];
    uint32_t aoff[2], boff[2];
#pragma unroll
    for (int i = 0; i < 2; i++) {
        int idx = tid + 256 * i;
        int r = idx >> 2, cg = idx & 3;
        int row;
        if (MODE == 1) { int rr = bm + r; if (rr >= cnt) rr = cnt - 1; row = g_perm[base + rr]; }
        else row = bm + r;
        aptr[i] = A + (size_t)row * K + cg * 8;
        bgp[i]  = BG + (size_t)(bn + r) * K + cg * 8;
        bup[i]  = BU + (size_t)(bn + r) * K + cg * 8;
        aoff[i] = (uint32_t)(r * HSTR + cg * 4) * 4;
        boff[i] = (uint32_t)(HTILE + r * HSTR + cg * 4) * 4;
    }

#pragma unroll
    for (int i = 0; i < 2; i++) {
        cpa16(smb + aoff[i], aptr[i]);
        cpa16(smb + boff[i], bgp[i]);
        cpa16(smb + HTILE * 4 + boff[i], bup[i]);
    }
    CP_COMMIT();

    float accg[2][8][4], accu[2][8][4];
#pragma unroll
    for (int mt = 0; mt < 2; mt++)
#pragma unroll
        for (int nt = 0; nt < 8; nt++)
#pragma unroll
            for (int q = 0; q < 4; q++) { accg[mt][nt][q] = 0.f; accu[mt][nt][q] = 0.f; }

    const int abase = (wm * 32 + g) * HSTR + tig;
    const int bbase = (wn * 64 + g) * HSTR + tig;
    const int KC = K / 32;

    for (int c = 0; c < KC; c++) {
        int s = c & 1;
        bool more = (c + 1 < KC);
        if (more) {
            uint32_t nb = smb + (uint32_t)(s ^ 1) * GSTG * 4;
#pragma unroll
            for (int i = 0; i < 2; i++) {
                cpa16(nb + aoff[i], aptr[i] + (c + 1) * 32);
                cpa16(nb + boff[i], bgp[i] + (c + 1) * 32);
                cpa16(nb + HTILE * 4 + boff[i], bup[i] + (c + 1) * 32);
            }
            CP_COMMIT();
            CP_WAIT1();
        } else {
            CP_WAIT0();
        }
        __syncthreads();

        const uint32_t* AH = SM + s * GSTG;
        const uint32_t* BGs = AH + HTILE;
        const uint32_t* BUs = AH + 2 * HTILE;

#pragma unroll
        for (int ks = 0; ks < 2; ks++) {
            uint32_t ah[2][4];
#pragma unroll
            for (int mt = 0; mt < 2; mt++) {
                int a0 = abase + mt * 16 * HSTR + ks * 8;
                ah[mt][0] = AH[a0];
                ah[mt][1] = AH[a0 + 8 * HSTR];
                ah[mt][2] = AH[a0 + 4];
                ah[mt][3] = AH[a0 + 8 * HSTR + 4];
            }
#pragma unroll
            for (int nt = 0; nt < 8; nt++) {
                int b0i = bbase + nt * 8 * HSTR + ks * 8;
                uint32_t bg0 = BGs[b0i], bg1 = BGs[b0i + 4];
                uint32_t bu0 = BUs[b0i], bu1 = BUs[b0i + 4];
#pragma unroll
                for (int mt = 0; mt < 2; mt++) {
                    MMA_F16(accg[mt][nt], ah[mt], bg0, bg1);
                    MMA_F16(accu[mt][nt], ah[mt], bu0, bu1);
                }
            }
        }
        __syncthreads();
    }

#pragma unroll
    for (int mt = 0; mt < 2; mt++) {
        int mloc0 = wm * 32 + mt * 16 + g;
#pragma unroll
        for (int nt = 0; nt < 8; nt++) {
            int col = bn + wn * 64 + nt * 8 + 2 * tig;
            float* dg = accg[mt][nt];
            float* du = accu[mt][nt];
            float h0 = (dg[0] / (1.0f + __expf(-dg[0]))) * du[0];
            float h1 = (dg[1] / (1.0f + __expf(-dg[1]))) * du[1];
            float h2 = (dg[2] / (1.0f + __expf(-dg[2]))) * du[2];
            float h3 = (dg[3] / (1.0f + __expf(-dg[3]))) * du[3];
            uint32_t p0 = packh2(h0, h1);
            uint32_t p1 = packh2(h2, h3);
            if (MODE == 0) {
                size_t i0 = (size_t)(bm + mloc0) * N + col;
                size_t i1 = (size_t)(bm + mloc0 + 8) * N + col;
                *(uint32_t*)&C[i0] = p0;
                *(uint32_t*)&C[i1] = p1;
            } else {
                if (bm + mloc0 < cnt) {
                    size_t i0 = (size_t)(base + bm + mloc0) * N + col;
                    *(uint32_t*)&C[i0] = p0;
                }
                if (bm + mloc0 + 8 < cnt) {
                    size_t i1 = (size_t)(base + bm + mloc0 + 8) * N + col;
                    *(uint32_t*)&C[i1] = p1;
                }
            }
        }
    }
}

// ---------------- double-fp16 compensated GEMM (router-upstream, unchanged) ----------------
#define HCSTG (4 * HTILE)
#define SMEM_HC (2 * HCSTG * 4)

__global__ void __launch_bounds__(256) gemm_hc(
    const float* __restrict__ A, const __half* __restrict__ BHI,
    const __half* __restrict__ BLO, float* __restrict__ C,
    int M, int N, int K, const float* __restrict__ Res)
{
    int bm = blockIdx.y * 128, bn = blockIdx.x * 128;
    int tid = threadIdx.x, lane = tid & 31, warp = tid >> 5;
    int wm = warp & 3, wn = warp >> 2;
    int g = lane >> 2, tig = lane & 3;

    extern __shared__ __align__(16) float smf[];
    uint32_t smb = smem_u32(smf);
    const uint32_t* SM = (const uint32_t*)smf;

    const float* aptr[2]; const __half* bhp[2]; const __half* blp[2];
    uint32_t aoff[2], boff[2];
#pragma unroll
    for (int i = 0; i < 2; i++) {
        int idx = tid + 256 * i;
        int r = idx >> 2, cg = idx & 3;
        aptr[i] = A + (size_t)(bm + r) * K + cg * 8;
        bhp[i]  = BHI + (size_t)(bn + r) * K + cg * 8;
        blp[i]  = BLO + (size_t)(bn + r) * K + cg * 8;
        aoff[i] = (uint32_t)(r * HSTR + cg * 4) * 4;
        boff[i] = (uint32_t)(HTILE + r * HSTR + cg * 4) * 4;
    }

    float4 areg[2][2];
#pragma unroll
    for (int i = 0; i < 2; i++) {
        areg[i][0] = *(const float4*)(aptr[i]);
        areg[i][1] = *(const float4*)(aptr[i] + 4);
        cpa16(smb + boff[i], bhp[i]);
        cpa16(smb + 2 * HTILE * 4 + boff[i], blp[i]);
    }
    CP_COMMIT();
#pragma unroll
    for (int i = 0; i < 2; i++) {
        float x0 = areg[i][0].x, x1 = areg[i][0].y, x2 = areg[i][0].z, x3 = areg[i][0].w;
        float x4 = areg[i][1].x, x5 = areg[i][1].y, x6 = areg[i][1].z, x7 = areg[i][1].w;
        float h0 = __half2float(__float2half_rn(x0)), h1 = __half2float(__float2half_rn(x1));
        float h2 = __half2float(__float2half_rn(x2)), h3 = __half2float(__float2half_rn(x3));
        float h4 = __half2float(__float2half_rn(x4)), h5 = __half2float(__float2half_rn(x5));
        float h6 = __half2float(__float2half_rn(x6)), h7 = __half2float(__float2half_rn(x7));
        uint32_t a0 = packh2(x0, x1), a1 = packh2(x2, x3), a2 = packh2(x4, x5), a3 = packh2(x6, x7);
        uint32_t l0 = packh2((x0 - h0) * LOSCALE, (x1 - h1) * LOSCALE);
        uint32_t l1 = packh2((x2 - h2) * LOSCALE, (x3 - h3) * LOSCALE);
        uint32_t l2 = packh2((x4 - h4) * LOSCALE, (x5 - h5) * LOSCALE);
        uint32_t l3 = packh2((x6 - h6) * LOSCALE, (x7 - h7) * LOSCALE);
        asm volatile("st.shared.v4.b32 [%0], {%1,%2,%3,%4};"
                     :: "r"(smb + aoff[i]), "r"(a0), "r"(a1), "r"(a2), "r"(a3) : "memory");
        asm volatile("st.shared.v4.b32 [%0], {%1,%2,%3,%4};"
                     :: "r"(smb + 2 * HTILE * 4 + aoff[i]), "r"(l0), "r"(l1), "r"(l2), "r"(l3) : "memory");
    }

    float acc1[2][8][4], acc2[2][8][4];
#pragma unroll
    for (int mt = 0; mt < 2; mt++)
#pragma unroll
        for (int nt = 0; nt < 8; nt++)
#pragma unroll
            for (int q = 0; q < 4; q++) { acc1[mt][nt][q] = 0.f; acc2[mt][nt][q] = 0.f; }

    const int abase = (wm * 32 + g) * HSTR + tig;
    const int bbase = (wn * 64 + g) * HSTR + tig;
    const int KC = K / 32;

    for (int c = 0; c < KC; c++) {
        int s = c & 1;
        bool more = (c + 1 < KC);
        if (more) {
            uint32_t nb = smb + (uint32_t)(s ^ 1) * HCSTG * 4;
#pragma unroll
            for (int i = 0; i < 2; i++) {
                areg[i][0] = *(const float4*)(aptr[i] + (c + 1) * 32);
                areg[i][1] = *(const float4*)(aptr[i] + (c + 1) * 32 + 4);
                cpa16(nb + boff[i], bhp[i] + (c + 1) * 32);
                cpa16(nb + 2 * HTILE * 4 + boff[i], blp[i] + (c + 1) * 32);
            }
            CP_COMMIT();
            CP_WAIT1();
        } else {
            CP_WAIT0();
        }
        __syncthreads();

        const uint32_t* AH = SM + s * HCSTG;
        const uint32_t* BH = AH + HTILE;
        const uint32_t* AL = AH + 2 * HTILE;
        const uint32_t* BL = AH + 3 * HTILE;

#pragma unroll
        for (int ks = 0; ks < 2; ks++) {
            uint32_t ah[2][4], al[2][4];
#pragma unroll
            for (int mt = 0; mt < 2; mt++) {
                int a0 = abase + mt * 16 * HSTR + ks * 8;
                ah[mt][0] = AH[a0];            ah[mt][1] = AH[a0 + 8 * HSTR];
                ah[mt][2] = AH[a0 + 4];        ah[mt][3] = AH[a0 + 8 * HSTR + 4];
                al[mt][0] = AL[a0];            al[mt][1] = AL[a0 + 8 * HSTR];
                al[mt][2] = AL[a0 + 4];        al[mt][3] = AL[a0 + 8 * HSTR + 4];
            }
#pragma unroll
            for (int nt = 0; nt < 8; nt++) {
                int b0i = bbase + nt * 8 * HSTR + ks * 8;
                uint32_t b0 = BH[b0i], b1 = BH[b0i + 4];
                uint32_t c0 = BL[b0i], c1 = BL[b0i + 4];
#pragma unroll
                for (int mt = 0; mt < 2; mt++) {
                    MMA_F16(acc1[mt][nt], ah[mt], b0, b1);
                    MMA_F16(acc2[mt][nt], ah[mt], c0, c1);
                    MMA_F16(acc2[mt][nt], al[mt], b0, b1);
                }
            }
        }
        __syncthreads();

        if (more) {
            uint32_t nb = smb + (uint32_t)(s ^ 1) * HCSTG * 4;
#pragma unroll
            for (int i = 0; i < 2; i++) {
                float x0 = areg[i][0].x, x1 = areg[i][0].y, x2 = areg[i][0].z, x3 = areg[i][0].w;
                float x4 = areg[i][1].x, x5 = areg[i][1].y, x6 = areg[i][1].z, x7 = areg[i][1].w;
                float h0 = __half2float(__float2half_rn(x0)), h1 = __half2float(__float2half_rn(x1));
                float h2 = __half2float(__float2half_rn(x2)), h3 = __half2float(__float2half_rn(x3));
                float h4 = __half2float(__float2half_rn(x4)), h5 = __half2float(__float2half_rn(x5));
                float h6 = __half2float(__float2half_rn(x6)), h7 = __half2float(__float2half_rn(x7));
                uint32_t a0 = packh2(x0, x1), a1 = packh2(x2, x3), a2 = packh2(x4, x5), a3 = packh2(x6, x7);
                uint32_t l0 = packh2((x0 - h0) * LOSCALE, (x1 - h1) * LOSCALE);
                uint32_t l1 = packh2((x2 - h2) * LOSCALE, (x3 - h3) * LOSCALE);
                uint32_t l2 = packh2((x4 - h4) * LOSCALE, (x5 - h5) * LOSCALE);
                uint32_t l3 = packh2((x6 - h6) * LOSCALE, (x7 - h7) * LOSCALE);
                asm volatile("st.shared.v4.b32 [%0], {%1,%2,%3,%4};"
                             :: "r"(nb + aoff[i]), "r"(a0), "r"(a1), "r"(a2), "r"(a3) : "memory");
                asm volatile("st.shared.v4.b32 [%0], {%1,%2,%3,%4};"
                             :: "r"(nb + 2 * HTILE * 4 + aoff[i]), "r"(l0), "r"(l1), "r"(l2), "r"(l3) : "memory");
            }
        }
    }

#pragma unroll
    for (int mt = 0; mt < 2; mt++) {
        int mloc0 = wm * 32 + mt * 16 + g;
#pragma unroll
        for (int nt = 0; nt < 8; nt++) {
            int col = bn + wn * 64 + nt * 8 + 2 * tig;
            float* d1 = acc1[mt][nt];
            float* d2 = acc2[mt][nt];
            size_t i0 = (size_t)(bm + mloc0) * N + col;
            size_t i1 = (size_t)(bm + mloc0 + 8) * N + col;
            float2 v0 = make_float2(d1[0] + d2[0] * INVLOSCALE, d1[1] + d2[1] * INVLOSCALE);
            float2 v1 = make_float2(d1[2] + d2[2] * INVLOSCALE, d1[3] + d2[3] * INVLOSCALE);
            if (Res) {
                float2 r0 = *(const float2*)&Res[i0];
                float2 r1 = *(const float2*)&Res[i1];
                v0.x += r0.x; v0.y += r0.y; v1.x += r1.x; v1.y += r1.y;
            }
            *(float2*)&C[i0] = v0;
            *(float2*)&C[i1] = v1;
        }
    }
}

// ---------------- warp-per-token rmsnorms ----------------
__global__ __launch_bounds__(256) void rmsnorm_kernel(
    const float* __restrict__ x, const float* __restrict__ w, float* __restrict__ o)
{
    int warp = threadIdx.x >> 5, lane = threadIdx.x & 31;
    int t = blockIdx.x * 8 + warp;
    const float4* xr = (const float4*)(x + (size_t)t * HHD);
    const float4* wr = (const float4*)w;
    float4* orr = (float4*)(o + (size_t)t * HHD);
    float ss = 0.f;
    float4 xv[16];
#pragma unroll
    for (int it = 0; it < 16; it++) {
        xv[it] = xr[it * 32 + lane];
        ss += xv[it].x * xv[it].x + xv[it].y * xv[it].y
            + xv[it].z * xv[it].z + xv[it].w * xv[it].w;
    }
#pragma unroll
    for (int off = 16; off; off >>= 1) ss += __shfl_xor_sync(~0u, ss, off);
    float scale = rsqrtf(ss / (float)HHD + EPSV);
#pragma unroll
    for (int it = 0; it < 16; it++) {
        float4 wv = wr[it * 32 + lane];
        float4 v = make_float4(xv[it].x * scale * wv.x, xv[it].y * scale * wv.y,
                               xv[it].z * scale * wv.z, xv[it].w * scale * wv.w);
        orr[it * 32 + lane] = v;
    }
}

__global__ __launch_bounds__(256) void rmsnorm_dual(
    const float* __restrict__ x, const float* __restrict__ w,
    float* __restrict__ o32, __half* __restrict__ o16)
{
    int warp = threadIdx.x >> 5, lane = threadIdx.x & 31;
    int t = blockIdx.x * 8 + warp;
    const float4* xr = (const float4*)(x + (size_t)t * HHD);
    const float4* wr = (const float4*)w;
    float4* o32r = (float4*)(o32 + (size_t)t * HHD);
    uint2* o16r = (uint2*)(o16 + (size_t)t * HHD);
    float ss = 0.f;
    float4 xv[16];
#pragma unroll
    for (int it = 0; it < 16; it++) {
        xv[it] = xr[it * 32 + lane];
        ss += xv[it].x * xv[it].x + xv[it].y * xv[it].y
            + xv[it].z * xv[it].z + xv[it].w * xv[it].w;
    }
#pragma unroll
    for (int off = 16; off; off >>= 1) ss += __shfl_xor_sync(~0u, ss, off);
    float scale = rsqrtf(ss / (float)HHD + EPSV);
#pragma unroll
    for (int it = 0; it < 16; it++) {
        float4 wv = wr[it * 32 + lane];
        float4 v = make_float4(xv[it].x * scale * wv.x, xv[it].y * scale * wv.y,
                               xv[it].z * scale * wv.z, xv[it].w * scale * wv.w);
        o32r[it * 32 + lane] = v;
        uint2 hh;
        hh.x = packh2(v.x, v.y);
        hh.y = packh2(v.z, v.w);
        o16r[it * 32 + lane] = hh;
    }
}

// ---------------- rope + q/k rmsnorm ----------------
__global__ __launch_bounds__(256) void ropenorm_kernel(
    float* __restrict__ qkv, const int* __restrict__ pos,
    const float* __restrict__ qw, const float* __restrict__ kw)
{
    int t = blockIdx.x, tid = threadIdx.x;
    float* row = qkv + (size_t)t * QKVN;
    float p = (float)pos[t];
    const float lgt = logf(500000.0f);
    __shared__ float red[256];
    __shared__ float sq, sk;

    float ss = 0.f;
    for (int idx = tid; idx < 1024; idx += 256) {
        int hh = idx >> 6, i = idx & 63;
        float inv = expf(-lgt * (float)i * (1.0f / 64.0f));
        float fr = p * inv, c = cosf(fr), s = sinf(fr);
        float x1 = row[hh * 128 + i], x2 = row[hh * 128 + 64 + i];
        float o1 = x1 * c - x2 * s, o2 = x2 * c + x1 * s;
        row[hh * 128 + i] = o1; row[hh * 128 + 64 + i] = o2;
        ss += o1 * o1 + o2 * o2;
    }
    red[tid] = ss; __syncthreads();
    for (int s2 = 128; s2 > 0; s2 >>= 1) { if (tid < s2) red[tid] += red[tid + s2]; __syncthreads(); }
    if (tid == 0) sq = rsqrtf(red[0] / (float)QSZ + EPSV);
    __syncthreads();

    float ssk = 0.f;
    {
        int hh = tid >> 6, i = tid & 63;
        float inv = expf(-lgt * (float)i * (1.0f / 64.0f));
        float fr = p * inv, c = cosf(fr), s = sinf(fr);
        float* kb = row + QSZ;
        float x1 = kb[hh * 128 + i], x2 = kb[hh * 128 + 64 + i];
        float o1 = x1 * c - x2 * s, o2 = x2 * c + x1 * s;
        kb[hh * 128 + i] = o1; kb[hh * 128 + 64 + i] = o2;
        ssk = o1 * o1 + o2 * o2;
    }
    red[tid] = ssk; __syncthreads();
    for (int s2 = 128; s2 > 0; s2 >>= 1) { if (tid < s2) red[tid] += red[tid + s2]; __syncthreads(); }
    if (tid == 0) sk = rsqrtf(red[0] / (float)KVSZ + EPSV);
    __syncthreads();

    for (int j = tid; j < QSZ; j += 256) row[j] *= sq * qw[j];
    for (int j = tid; j < KVSZ; j += 256) row[QSZ + j] *= sk * kw[j];
}

// ---------------- flash attention (fp32, BM=64, R13-proven) ----------------
#define QKSTR 132
#define PSTR  68
#define SMEM_ATTN ((3 * 64 * QKSTR + 64 * PSTR) * 4)

__global__ __launch_bounds__(256) void attn_kernel(
    const float* __restrict__ qkv, float* __restrict__ O)
{
    extern __shared__ float sh[];
    float* Qs = sh;
    float* Ks = sh + 64 * QKSTR;
    float* Vs = sh + 2 * 64 * QKSTR;
    float* Ps = sh + 3 * 64 * QKSTR;

    int m0 = ((int)gridDim.x - 1 - (int)blockIdx.x) * 64;
    int h  = blockIdx.y;
    int kvh = h >> 2;
    int tid = threadIdx.x, lane = tid & 31, w = tid >> 5;
    const float scl = 0.08838834764831845f;

    for (int i = tid; i < 2048; i += 256) {
        int r = i >> 5, c = (i & 31) << 2;
        *(float4*)&Qs[r * QKSTR + c] =
            *(const float4*)&qkv[(size_t)(m0 + r) * QKVN + h * HDIM + c];
    }

    float mrow[8], lrow[8], oacc[8][4];
#pragma unroll
    for (int r = 0; r < 8; r++) {
        mrow[r] = -1e30f; lrow[r] = 0.f;
        oacc[r][0] = oacc[r][1] = oacc[r][2] = oacc[r][3] = 0.f;
    }
    int d0 = lane << 2;

    for (int n0 = 0; n0 <= m0; n0 += 64) {
        __syncthreads();
        for (int i = tid; i < 2048; i += 256) {
            int r = i >> 5, c = (i & 31) << 2;
            *(float4*)&Ks[r * QKSTR + c] =
                *(const float4*)&qkv[(size_t)(n0 + r) * QKVN + QSZ + kvh * HDIM + c];
            *(float4*)&Vs[r * QKSTR + c] =
                *(const float4*)&qkv[(size_t)(n0 + r) * QKVN + QSZ + KVSZ + kvh * HDIM + c];
        }
        __syncthreads();

        float s0[8] = {0,0,0,0,0,0,0,0};
        float s1[8] = {0,0,0,0,0,0,0,0};
#pragma unroll 4
        for (int k = 0; k < 128; k += 4) {
            float4 k0 = *(float4*)&Ks[lane * QKSTR + k];
            float4 k1 = *(float4*)&Ks[(lane + 32) * QKSTR + k];
#pragma unroll
            for (int r = 0; r < 8; r++) {
                float4 q = *(float4*)&Qs[(w * 8 + r) * QKSTR + k];
                s0[r] += q.x * k0.x + q.y * k0.y + q.z * k0.z + q.w * k0.w;
                s1[r] += q.x * k1.x + q.y * k1.y + q.z * k1.z + q.w * k1.w;
            }
        }
        bool diag = (n0 + 63 > m0);
#pragma unroll
        for (int r = 0; r < 8; r++) {
            int grow = m0 + w * 8 + r;
            float v0 = s0[r] * scl, v1 = s1[r] * scl;
            if (diag) {
                if (n0 + lane      > grow) v0 = -1e30f;
                if (n0 + lane + 32 > grow) v1 = -1e30f;
            }
            float tmax = fmaxf(v0, v1);
#pragma unroll
            for (int o = 16; o; o >>= 1) tmax = fmaxf(tmax, __shfl_xor_sync(~0u, tmax, o));
            float nm = fmaxf(mrow[r], tmax);
            float p0 = __expf(v0 - nm), p1 = __expf(v1 - nm);
            float corr = __expf(mrow[r] - nm);
            float psum = p0 + p1;
#pragma unroll
            for (int o = 16; o; o >>= 1) psum += __shfl_xor_sync(~0u, psum, o);
            lrow[r] = lrow[r] * corr + psum;
            mrow[r] = nm;
            oacc[r][0] *= corr; oacc[r][1] *= corr; oacc[r][2] *= corr; oacc[r][3] *= corr;
            Ps[(w * 8 + r) * PSTR + lane]      = p0;
            Ps[(w * 8 + r) * PSTR + lane + 32] = p1;
        }
        __syncwarp();
#pragma unroll 2
        for (int n = 0; n < 64; n += 4) {
            float4 v0 = *(float4*)&Vs[(n + 0) * QKSTR + d0];
            float4 v1 = *(float4*)&Vs[(n + 1) * QKSTR + d0];
            float4 v2 = *(float4*)&Vs[(n + 2) * QKSTR + d0];
            float4 v3 = *(float4*)&Vs[(n + 3) * QKSTR + d0];
#pragma unroll
            for (int r = 0; r < 8; r++) {
                float4 pv = *(float4*)&Ps[(w * 8 + r) * PSTR + n];
                oacc[r][0] += pv.x * v0.x + pv.y * v1.x + pv.z * v2.x + pv.w * v3.x;
                oacc[r][1] += pv.x * v0.y + pv.y * v1.y + pv.z * v2.y + pv.w * v3.y;
                oacc[r][2] += pv.x * v0.z + pv.y * v1.z + pv.z * v2.z + pv.w * v3.z;
                oacc[r][3] += pv.x * v0.w + pv.y * v1.w + pv.z * v2.w + pv.w * v3.w;
            }
        }
    }
#pragma unroll
    for (int r = 0; r < 8; r++) {
        float inv = 1.0f / lrow[r];
        float4 o = make_float4(oacc[r][0] * inv, oacc[r][1] * inv,
                               oacc[r][2] * inv, oacc[r][3] * inv);
        *(float4*)&O[(size_t)(m0 + w * 8 + r) * QSZ + h * HDIM + d0] = o;
    }
}

// ---------------- router / permutation ----------------
__global__ void zero_kernel()
{
    int i = threadIdx.x;
    if (i < NEXP) { g_cnt[i] = 0; g_cur[i] = 0; }
}

__global__ __launch_bounds__(256) void router_kernel(
    const float* __restrict__ y, const float* __restrict__ rw)
{
    int warp = threadIdx.x >> 5, lane = threadIdx.x & 31;
    int t = blockIdx.x * 8 + warp;
    const float4* xr = (const float4*)(y + (size_t)t * HHD);
    float part[NEXP] = {};
#pragma unroll 4
    for (int it = 0; it < 16; it++) {
        int kq = it * 32 + lane;
        float4 xv = xr[kq];
        const float* r0 = rw + (size_t)(kq * 4) * NEXP;
#pragma unroll
        for (int e = 0; e < NEXP; e++)
            part[e] += xv.x * r0[e] + xv.y * r0[NEXP + e]
                     + xv.z * r0[2 * NEXP + e] + xv.w * r0[3 * NEXP + e];
    }
#pragma unroll
    for (int e = 0; e < NEXP; e++)
#pragma unroll
        for (int o = 16; o; o >>= 1) part[e] += __shfl_xor_sync(~0u, part[e], o);
    if (lane == 0) {
        int am = 0; float mv = part[0];
#pragma unroll
        for (int e = 1; e < NEXP; e++) if (part[e] > mv) { mv = part[e]; am = e; }
        g_expert[t] = am;
        g_gate[t]   = 1.0f / (1.0f + expf(-mv));
        atomicAdd(&g_cnt[am], 1);
    }
}

__global__ void scan_kernel()
{
    int s = 0;
    for (int e = 0; e < NEXP; e++) { g_off[e] = s; s += g_cnt[e]; }
}

__global__ void scatter_kernel()
{
    int t = blockIdx.x * 256 + threadIdx.x;
    if (t >= TT) return;
    int e = g_expert[t];
    int p = atomicAdd(&g_cur[e], 1);
    g_perm[g_off[e] + p] = t;
}

// ---------------- launcher ----------------
extern "C" void kernel_launch(void* const* d_in, const int* in_sizes, int n_in,
                              void* d_out, int out_size)
{
    const int*   positions = (const int*)  d_in[0];
    const float* hidden    = (const float*)d_in[1];
    const float* ln1       = (const float*)d_in[2];
    const float* ln2       = (const float*)d_in[3];
    const float* w_qkv     = (const float*)d_in[4];
    const float* w_o       = (const float*)d_in[5];
    const float* qnw       = (const float*)d_in[6];
    const float* knw       = (const float*)d_in[7];
    const float* rw        = (const float*)d_in[8];
    const float* wsg       = (const float*)d_in[9];
    const float* wsu       = (const float*)d_in[10];
    const float* wsd       = (const float*)d_in[11];
    const float* weg       = (const float*)d_in[12];
    const float* weu       = (const float*)d_in[13];
    const float* wed       = (const float*)d_in[14];
    float* out = (float*)d_out;

    void* p;
    cudaGetSymbolAddress(&p, g_xn);  float* xn  = (float*)p;
    cudaGetSymbolAddress(&p, g_qkv); float* qkv = (float*)p;
    cudaGetSymbolAddress(&p, g_att); float* att = (float*)p;
    cudaGetSymbolAddress(&p, g_x2);  float* x2  = (float*)p;
    cudaGetSymbolAddress(&p, g_y);   float* y   = (float*)p;
    cudaGetSymbolAddress(&p, g_y16); __half* y16 = (__half*)p;
    cudaGetSymbolAddress(&p, g_g);   __half* gg16 = (__half*)p;
    cudaGetSymbolAddress(&p, g_wqkvT);  __half* wqkvT  = (__half*)p;
    cudaGetSymbolAddress(&p, g_wqkvTl); __half* wqkvTl = (__half*)p;
    cudaGetSymbolAddress(&p, g_woT);    __half* woT    = (__half*)p;
    cudaGetSymbolAddress(&p, g_woTl);   __half* woTl   = (__half*)p;
    cudaGetSymbolAddress(&p, g_wsgT);   __half* wsgT   = (__half*)p;
    cudaGetSymbolAddress(&p, g_wsuT);   __half* wsuT   = (__half*)p;
    cudaGetSymbolAddress(&p, g_wsdT);   __half* wsdT   = (__half*)p;
    cudaGetSymbolAddress(&p, g_wegT);   __half* wegT   = (__half*)p;
    cudaGetSymbolAddress(&p, g_weuT);   __half* weuT   = (__half*)p;
    cudaGetSymbolAddress(&p, g_wedT);   __half* wedT   = (__half*)p;

    cudaFuncSetAttribute(attn_kernel, cudaFuncAttributeMaxDynamicSharedMemorySize, SMEM_ATTN);
    cudaFuncSetAttribute(gemm_hc, cudaFuncAttributeMaxDynamicSharedMemorySize, SMEM_HC);
    cudaFuncSetAttribute(gemm_h<0>, cudaFuncAttributeMaxDynamicSharedMemorySize, SMEM_H);
    cudaFuncSetAttribute(gemm_h<2>, cudaFuncAttributeMaxDynamicSharedMemorySize, SMEM_H);
    cudaFuncSetAttribute(gemm_gu<0>, cudaFuncAttributeMaxDynamicSharedMemorySize, SMEM_GU);
    cudaFuncSetAttribute(gemm_gu<1>, cudaFuncAttributeMaxDynamicSharedMemorySize, SMEM_GU);

    // weight prep
    transpose_split_h<<<dim3(QKVN / 64, HHD / 64), 256>>>(w_qkv, wqkvT, wqkvTl, HHD, QKVN);
    transpose_split_h<<<dim3(HHD / 64, QSZ / 64), 256>>>(w_o, woT, woTl, QSZ, HHD);
    transpose_f16<<<dim3(II / 64, HHD / 64), 256>>>(wsg, wsgT, HHD, II);
    transpose_f16<<<dim3(II / 64, HHD / 64), 256>>>(wsu, wsuT, HHD, II);
    transpose_f16<<<dim3(HHD / 64, II / 64), 256>>>(wsd, wsdT, II, HHD);
    transpose_f16<<<dim3(II / 64, HHD / 64, NEXP), 256>>>(weg, wegT, HHD, II);
    transpose_f16<<<dim3(II / 64, HHD / 64, NEXP), 256>>>(weu, weuT, HHD, II);
    transpose_f16<<<dim3(HHD / 64, II / 64, NEXP), 256>>>(wed, wedT, II, HHD);

    // 1. x = rmsnorm(hidden, ln1)
    rmsnorm_kernel<<<TT / 8, 256>>>(hidden, ln1, xn);
    // 2. qkv = x @ w_qkv   (double-fp16 compensated — upstream of router)
    gemm_hc<<<dim3(QKVN / 128, TT / 128), 256, SMEM_HC>>>(xn, wqkvT, wqkvTl, qkv, TT, QKVN, HHD, nullptr);
    // 3. rope + q/k norm
    ropenorm_kernel<<<TT, 256>>>(qkv, positions, qnw, knw);
    // 4. attention (BM=64, proven)
    attn_kernel<<<dim3(TT / 64, NHEADS), 256, SMEM_ATTN>>>(qkv, att);
    // 5. x2 = hidden + attn @ w_o   (compensated)
    gemm_hc<<<dim3(HHD / 128, TT / 128), 256, SMEM_HC>>>(att, woT, woTl, x2, TT, HHD, QSZ, hidden);
    // 6. y = rmsnorm(x2, ln2)  -> fp32 (router) + fp16 (GEMM A)
    rmsnorm_dual<<<TT / 8, 256>>>(x2, ln2, y, y16);
    // 7. router (fp32, warp-per-token)
    zero_kernel<<<1, 32>>>();
    router_kernel<<<TT / 8, 256>>>(y, rw);
    scan_kernel<<<1, 1>>>();
    scatter_kernel<<<TT / 256, 256>>>();
    // 8. shared expert: fused gate+up+silu (fp16 out), then down (+x2 residual)
    gemm_gu<0><<<dim3(II / 128, TT / 128), 256, SMEM_GU>>>(y16, wsgT, wsuT, gg16, TT, II, HHD);
    gemm_h<0><<<dim3(HHD / 128, TT / 128), 256, SMEM_H>>>(gg16, wsdT, out, TT, HHD, II, x2);
    // 9. routed experts: fused grouped gate+up+silu, then grouped scatter-add down
    gemm_gu<1><<<dim3(II / 128, TT / 128, NEXP), 256, SMEM_GU>>>(y16, wegT, weuT, gg16, TT, II, HHD);
    gemm_h<2><<<dim3(HHD / 128, TT / 128, NEXP), 256, SMEM_H>>>(gg16, wedT, out, TT, HHD, II, nullptr);
}

// round 17
// speedup vs baseline: 1.0153x; 1.0048x over previous
#include <cuda_runtime.h>
#include <cuda_fp16.h>
#include <math.h>
#include <stdint.h>

#define TT     2048
#define HHD    2048
#define NHEADS 16
#define HDIM   128
#define QSZ    2048
#define KVSZ   512
#define QKVN   3072
#define NEXP   8
#define II     4096
#define EPSV   1e-5f

// ---------------- device scratch ----------------
__device__ __align__(256) float g_xn  [TT * HHD];    // used as fp16 hi/lo pair
__device__ __align__(256) float g_qkv [TT * QKVN];
__device__ __align__(256) float g_att [TT * QSZ];    // used as fp16 hi/lo pair
__device__ __align__(256) float g_x2  [TT * HHD];
__device__ __align__(256) float g_y   [TT * HHD];
__device__ __align__(256) float g_y16 [TT * HHD / 2];
__device__ __align__(256) float g_g   [TT * II / 2];
__device__ int   g_expert[TT];
__device__ float g_gate  [TT];
__device__ int   g_cnt[NEXP];
__device__ int   g_off[NEXP];
__device__ int   g_cur[NEXP];
__device__ int   g_perm[TT];
__device__ __align__(256) float g_wqkvT [QKVN * HHD / 2];
__device__ __align__(256) float g_wqkvTl[QKVN * HHD / 2];
__device__ __align__(256) float g_woT   [HHD * QSZ / 2];
__device__ __align__(256) float g_woTl  [HHD * QSZ / 2];
__device__ __align__(256) float g_wsgT  [II * HHD / 2];
__device__ __align__(256) float g_wsuT  [II * HHD / 2];
__device__ __align__(256) float g_wsdT  [HHD * II / 2];
__device__ __align__(256) float g_wegT  [NEXP * II * HHD / 2];
__device__ __align__(256) float g_weuT  [NEXP * II * HHD / 2];
__device__ __align__(256) float g_wedT  [NEXP * HHD * II / 2];

#define LOSCALE 1024.0f
#define INVLOSCALE (1.0f / 1024.0f)

// ---------------- helpers ----------------
__device__ __forceinline__ uint32_t smem_u32(const void* p) {
    uint32_t a;
    asm("{ .reg .u64 t; cvta.to.shared.u64 t, %1; cvt.u32.u64 %0, t; }" : "=r"(a) : "l"(p));
    return a;
}
__device__ __forceinline__ uint32_t packh2(float a, float b) {
    __half2 h = __floats2half2_rn(a, b);
    return *(uint32_t*)&h;
}
__device__ __forceinline__ void cpa16(uint32_t dst, const void* src) {
    asm volatile("cp.async.cg.shared.global [%0], [%1], 16;" :: "r"(dst), "l"(src) : "memory");
}
#define CP_COMMIT() asm volatile("cp.async.commit_group;" ::: "memory")
#define CP_WAIT1()  asm volatile("cp.async.wait_group 1;" ::: "memory")
#define CP_WAIT0()  asm volatile("cp.async.wait_group 0;" ::: "memory")

#define MMA_F16(d, a, b0, b1) \
  asm volatile("mma.sync.aligned.m16n8k16.row.col.f32.f16.f16.f32 " \
    "{%0,%1,%2,%3}, {%4,%5,%6,%7}, {%8,%9}, {%0,%1,%2,%3};" \
    : "+f"((d)[0]), "+f"((d)[1]), "+f"((d)[2]), "+f"((d)[3]) \
    : "r"((a)[0]), "r"((a)[1]), "r"((a)[2]), "r"((a)[3]), "r"(b0), "r"(b1))

// ---------------- transposes (stride-65 smem) ----------------
__global__ __launch_bounds__(256) void transpose_f16(
    const float* __restrict__ in, __half* __restrict__ out, int R, int C)
{
    __shared__ float t[64 * 65];
    in  += (size_t)blockIdx.z * (size_t)R * C;
    out += (size_t)blockIdx.z * (size_t)R * C;
    int c0 = blockIdx.x * 64, r0 = blockIdx.y * 64;
#pragma unroll
    for (int it = 0; it < 4; it++) {
        int idx = threadIdx.x + 256 * it;
        int r = idx >> 4, cq = (idx & 15) << 2;
        float4 v = *(const float4*)&in[(size_t)(r0 + r) * C + c0 + cq];
        t[(cq + 0) * 65 + r] = v.x;
        t[(cq + 1) * 65 + r] = v.y;
        t[(cq + 2) * 65 + r] = v.z;
        t[(cq + 3) * 65 + r] = v.w;
    }
    __syncthreads();
#pragma unroll
    for (int it = 0; it < 4; it++) {
        int idx = threadIdx.x + 256 * it;
        int c = idx >> 4, q = (idx & 15) << 2;
        uint2 v;
        v.x = packh2(t[c * 65 + q + 0], t[c * 65 + q + 1]);
        v.y = packh2(t[c * 65 + q + 2], t[c * 65 + q + 3]);
        *(uint2*)&out[(size_t)(c0 + c) * R + r0 + q] = v;
    }
}

__global__ __launch_bounds__(256) void transpose_split_h(
    const float* __restrict__ in, __half* __restrict__ hi, __half* __restrict__ lo,
    int R, int C)
{
    __shared__ float t[64 * 65];
    int c0 = blockIdx.x * 64, r0 = blockIdx.y * 64;
#pragma unroll
    for (int it = 0; it < 4; it++) {
        int idx = threadIdx.x + 256 * it;
        int r = idx >> 4, cq = (idx & 15) << 2;
        float4 v = *(const float4*)&in[(size_t)(r0 + r) * C + c0 + cq];
        t[(cq + 0) * 65 + r] = v.x;
        t[(cq + 1) * 65 + r] = v.y;
        t[(cq + 2) * 65 + r] = v.z;
        t[(cq + 3) * 65 + r] = v.w;
    }
    __syncthreads();
#pragma unroll
    for (int it = 0; it < 4; it++) {
        int idx = threadIdx.x + 256 * it;
        int c = idx >> 4, q = (idx & 15) << 2;
        float x0 = t[c * 65 + q + 0], x1 = t[c * 65 + q + 1];
        float x2 = t[c * 65 + q + 2], x3 = t[c * 65 + q + 3];
        float h0 = __half2float(__float2half_rn(x0));
        float h1 = __half2float(__float2half_rn(x1));
        float h2 = __half2float(__float2half_rn(x2));
        float h3 = __half2float(__float2half_rn(x3));
        uint2 vh, vl;
        vh.x = packh2(x0, x1);
        vh.y = packh2(x2, x3);
        vl.x = packh2((x0 - h0) * LOSCALE, (x1 - h1) * LOSCALE);
        vl.y = packh2((x2 - h2) * LOSCALE, (x3 - h3) * LOSCALE);
        size_t o = (size_t)(c0 + c) * R + r0 + q;
        *(uint2*)&hi[o] = vh;
        *(uint2*)&lo[o] = vl;
    }
}

// ---------------- fp16 GEMM (plain, fp16 A): 2-stage all-cp.async ----------------
#define HSTR 20
#define HTILE (128 * HSTR)
#define HSTG  (2 * HTILE)
#define SMEM_H (2 * HSTG * 4)

template<int MODE>
__global__ void __launch_bounds__(256) gemm_h(
    const __half* __restrict__ A, const __half* __restrict__ BT,
    float* __restrict__ C, int M, int N, int K, const float* __restrict__ Res)
{
    int e = blockIdx.z;
    int cnt = M, base = 0;
    if (MODE) {
        cnt = g_cnt[e]; base = g_off[e];
        if ((int)blockIdx.y * 128 >= cnt) return;
        BT += (size_t)e * (size_t)N * K;
    }
    int bm = blockIdx.y * 128, bn = blockIdx.x * 128;
    int tid = threadIdx.x, lane = tid & 31, warp = tid >> 5;
    int wm = warp & 3, wn = warp >> 2;
    int g = lane >> 2, tig = lane & 3;

    extern __shared__ __align__(16) float smf[];
    uint32_t smb = smem_u32(smf);
    const uint32_t* SM = (const uint32_t*)smf;

    const __half* aptr[2]; const __half* bptr[2];
    uint32_t aoff[2], boff[2];
#pragma unroll
    for (int i = 0; i < 2; i++) {
        int idx = tid + 256 * i;
        int r = idx >> 2, cg = idx & 3;
        int row;
        if (MODE == 1) { int rr = bm + r; if (rr >= cnt) rr = cnt - 1; row = g_perm[base + rr]; }
        else if (MODE == 2) { int rr = bm + r; if (rr >= cnt) rr = cnt - 1; row = base + rr; }
        else row = bm + r;
        aptr[i] = A + (size_t)row * K + cg * 8;
        bptr[i] = BT + (size_t)(bn + r) * K + cg * 8;
        aoff[i] = (uint32_t)(r * HSTR + cg * 4) * 4;
        boff[i] = (uint32_t)(HTILE + r * HSTR + cg * 4) * 4;
    }

#pragma unroll
    for (int i = 0; i < 2; i++) {
        cpa16(smb + aoff[i], aptr[i]);
        cpa16(smb + boff[i], bptr[i]);
    }
    CP_COMMIT();

    float acc[2][8][4];
#pragma unroll
    for (int mt = 0; mt < 2; mt++)
#pragma unroll
        for (int nt = 0; nt < 8; nt++)
#pragma unroll
            for (int q = 0; q < 4; q++) acc[mt][nt][q] = 0.f;

    const int abase = (wm * 32 + g) * HSTR + tig;
    const int bbase = (wn * 64 + g) * HSTR + tig;
    const int KC = K / 32;

    for (int c = 0; c < KC; c++) {
        int s = c & 1;
        bool more = (c + 1 < KC);
        if (more) {
            uint32_t nb = smb + (uint32_t)(s ^ 1) * HSTG * 4;
#pragma unroll
            for (int i = 0; i < 2; i++) {
                cpa16(nb + aoff[i], aptr[i] + (c + 1) * 32);
                cpa16(nb + boff[i], bptr[i] + (c + 1) * 32);
            }
            CP_COMMIT();
            CP_WAIT1();
        } else {
            CP_WAIT0();
        }
        __syncthreads();

        const uint32_t* AH = SM + s * HSTG;
        const uint32_t* BH = AH + HTILE;

#pragma unroll
        for (int ks = 0; ks < 2; ks++) {
            uint32_t ah[2][4];
#pragma unroll
            for (int mt = 0; mt < 2; mt++) {
                int a0 = abase + mt * 16 * HSTR + ks * 8;
                ah[mt][0] = AH[a0];
                ah[mt][1] = AH[a0 + 8 * HSTR];
                ah[mt][2] = AH[a0 + 4];
                ah[mt][3] = AH[a0 + 8 * HSTR + 4];
            }
#pragma unroll
            for (int nt = 0; nt < 8; nt++) {
                int b0i = bbase + nt * 8 * HSTR + ks * 8;
                uint32_t b0 = BH[b0i], b1 = BH[b0i + 4];
#pragma unroll
                for (int mt = 0; mt < 2; mt++)
                    MMA_F16(acc[mt][nt], ah[mt], b0, b1);
            }
        }
        __syncthreads();
    }

#pragma unroll
    for (int mt = 0; mt < 2; mt++) {
        int mloc0 = wm * 32 + mt * 16 + g;
#pragma unroll
        for (int nt = 0; nt < 8; nt++) {
            int col = bn + wn * 64 + nt * 8 + 2 * tig;
            float* d = acc[mt][nt];
            if (MODE == 0) {
                size_t i0 = (size_t)(bm + mloc0) * N + col;
                size_t i1 = (size_t)(bm + mloc0 + 8) * N + col;
                float2 v0 = make_float2(d[0], d[1]);
                float2 v1 = make_float2(d[2], d[3]);
                if (Res) {
                    float2 r0 = *(const float2*)&Res[i0];
                    float2 r1 = *(const float2*)&Res[i1];
                    v0.x += r0.x; v0.y += r0.y; v1.x += r1.x; v1.y += r1.y;
                }
                *(float2*)&C[i0] = v0;
                *(float2*)&C[i1] = v1;
            } else {
                if (bm + mloc0 < cnt) {
                    int tok = g_perm[base + bm + mloc0];
                    float gt = g_gate[tok];
                    size_t i0 = (size_t)tok * N + col;
                    float2 o = *(const float2*)&C[i0];
                    o.x += gt * d[0]; o.y += gt * d[1];
                    *(float2*)&C[i0] = o;
                }
                if (bm + mloc0 + 8 < cnt) {
                    int tok = g_perm[base + bm + mloc0 + 8];
                    float gt = g_gate[tok];
                    size_t i1 = (size_t)tok * N + col;
                    float2 o = *(const float2*)&C[i1];
                    o.x += gt * d[2]; o.y += gt * d[3];
                    *(float2*)&C[i1] = o;
                }
            }
        }
    }
}

// ---------------- fused gate+up GEMM, fp16 A, silu -> fp16 C, 2-stage ----------------
#define GSTG (3 * HTILE)
#define SMEM_GU (2 * GSTG * 4)

template<int MODE>
__global__ void __launch_bounds__(256) gemm_gu(
    const __half* __restrict__ A, const __half* __restrict__ BG,
    const __half* __restrict__ BU, __half* __restrict__ C,
    int M, int N, int K)
{
    int e = blockIdx.z;
    int cnt = M, base = 0;
    if (MODE) {
        cnt = g_cnt[e]; base = g_off[e];
        if ((int)blockIdx.y * 128 >= cnt) return;
        BG += (size_t)e * (size_t)N * K;
        BU += (size_t)e * (size_t)N * K;
    }
    int bm = blockIdx.y * 128, bn = blockIdx.x * 128;
    int tid = threadIdx.x, lane = tid & 31, warp = tid >> 5;
    int wm = warp & 3, wn = warp >> 2;
    int g = lane >> 2, tig = lane & 3;

    extern __shared__ __align__(16) float smf[];
    uint32_t smb = smem_u32(smf);
    const uint32_t* SM = (const uint32_t*)smf;

    const __half* aptr[2]; const __half* bgp[2]; const __half* bup[2];
    uint32_t aoff[2], boff[2];
#pragma unroll
    for (int i = 0; i < 2; i++) {
        int idx = tid + 256 * i;
        int r = idx >> 2, cg = idx & 3;
        int row;
        if (MODE == 1) { int rr = bm + r; if (rr >= cnt) rr = cnt - 1; row = g_perm[base + rr]; }
        else row = bm + r;
        aptr[i] = A + (size_t)row * K + cg * 8;
        bgp[i]  = BG + (size_t)(bn + r) * K + cg * 8;
        bup[i]  = BU + (size_t)(bn + r) * K + cg * 8;
        aoff[i] = (uint32_t)(r * HSTR + cg * 4) * 4;
        boff[i] = (uint32_t)(HTILE + r * HSTR + cg * 4) * 4;
    }

#pragma unroll
    for (int i = 0; i < 2; i++) {
        cpa16(smb + aoff[i], aptr[i]);
        cpa16(smb + boff[i], bgp[i]);
        cpa16(smb + HTILE * 4 + boff[i], bup[i]);
    }
    CP_COMMIT();

    float accg[2][8][4], accu[2][8][4];
#pragma unroll
    for (int mt = 0; mt < 2; mt++)
#pragma unroll
        for (int nt = 0; nt < 8; nt++)
#pragma unroll
            for (int q = 0; q < 4; q++) { accg[mt][nt][q] = 0.f; accu[mt][nt][q] = 0.f; }

    const int abase = (wm * 32 + g) * HSTR + tig;
    const int bbase = (wn * 64 + g) * HSTR + tig;
    const int KC = K / 32;

    for (int c = 0; c < KC; c++) {
        int s = c & 1;
        bool more = (c + 1 < KC);
        if (more) {
            uint32_t nb = smb + (uint32_t)(s ^ 1) * GSTG * 4;
#pragma unroll
            for (int i = 0; i < 2; i++) {
                cpa16(nb + aoff[i], aptr[i] + (c + 1) * 32);
                cpa16(nb + boff[i], bgp[i] + (c + 1) * 32);
                cpa16(nb + HTILE * 4 + boff[i], bup[i] + (c + 1) * 32);
            }
            CP_COMMIT();
            CP_WAIT1();
        } else {
            CP_WAIT0();
        }
        __syncthreads();

        const uint32_t* AH = SM + s * GSTG;
        const uint32_t* BGs = AH + HTILE;
        const uint32_t* BUs = AH + 2 * HTILE;

#pragma unroll
        for (int ks = 0; ks < 2; ks++) {
            uint32_t ah[2][4];
#pragma unroll
            for (int mt = 0; mt < 2; mt++) {
                int a0 = abase + mt * 16 * HSTR + ks * 8;
                ah[mt][0] = AH[a0];
                ah[mt][1] = AH[a0 + 8 * HSTR];
                ah[mt][2] = AH[a0 + 4];
                ah[mt][3] = AH[a0 + 8 * HSTR + 4];
            }
#pragma unroll
            for (int nt = 0; nt < 8; nt++) {
                int b0i = bbase + nt * 8 * HSTR + ks * 8;
                uint32_t bg0 = BGs[b0i], bg1 = BGs[b0i + 4];
                uint32_t bu0 = BUs[b0i], bu1 = BUs[b0i + 4];
#pragma unroll
                for (int mt = 0; mt < 2; mt++) {
                    MMA_F16(accg[mt][nt], ah[mt], bg0, bg1);
                    MMA_F16(accu[mt][nt], ah[mt], bu0, bu1);
                }
            }
        }
        __syncthreads();
    }

#pragma unroll
    for (int mt = 0; mt < 2; mt++) {
        int mloc0 = wm * 32 + mt * 16 + g;
#pragma unroll
        for (int nt = 0; nt < 8; nt++) {
            int col = bn + wn * 64 + nt * 8 + 2 * tig;
            float* dg = accg[mt][nt];
            float* du = accu[mt][nt];
            float h0 = (dg[0] / (1.0f + __expf(-dg[0]))) * du[0];
            float h1 = (dg[1] / (1.0f + __expf(-dg[1]))) * du[1];
            float h2 = (dg[2] / (1.0f + __expf(-dg[2]))) * du[2];
            float h3 = (dg[3] / (1.0f + __expf(-dg[3]))) * du[3];
            uint32_t p0 = packh2(h0, h1);
            uint32_t p1 = packh2(h2, h3);
            if (MODE == 0) {
                size_t i0 = (size_t)(bm + mloc0) * N + col;
                size_t i1 = (size_t)(bm + mloc0 + 8) * N + col;
                *(uint32_t*)&C[i0] = p0;
                *(uint32_t*)&C[i1] = p1;
            } else {
                if (bm + mloc0 < cnt) {
                    size_t i0 = (size_t)(base + bm + mloc0) * N + col;
                    *(uint32_t*)&C[i0] = p0;
                }
                if (bm + mloc0 + 8 < cnt) {
                    size_t i1 = (size_t)(base + bm + mloc0 + 8) * N + col;
                    *(uint32_t*)&C[i1] = p1;
                }
            }
        }
    }
}

// ---------------- double-fp16 compensated GEMM (pre-split A, all-cp.async) ----------------
#define HCSTG (4 * HTILE)
#define SMEM_HC (2 * HCSTG * 4)

__global__ void __launch_bounds__(256) gemm_hc(
    const __half* __restrict__ AHI, const __half* __restrict__ ALO,
    const __half* __restrict__ BHI, const __half* __restrict__ BLO,
    float* __restrict__ C, int M, int N, int K, const float* __restrict__ Res)
{
    int bm = blockIdx.y * 128, bn = blockIdx.x * 128;
    int tid = threadIdx.x, lane = tid & 31, warp = tid >> 5;
    int wm = warp & 3, wn = warp >> 2;
    int g = lane >> 2, tig = lane & 3;

    extern __shared__ __align__(16) float smf[];
    uint32_t smb = smem_u32(smf);
    const uint32_t* SM = (const uint32_t*)smf;

    const __half* ahp[2]; const __half* alp[2];
    const __half* bhp[2]; const __half* blp[2];
    uint32_t aoff[2], boff[2];
#pragma unroll
    for (int i = 0; i < 2; i++) {
        int idx = tid + 256 * i;
        int r = idx >> 2, cg = idx & 3;
        ahp[i] = AHI + (size_t)(bm + r) * K + cg * 8;
        alp[i] = ALO + (size_t)(bm + r) * K + cg * 8;
        bhp[i] = BHI + (size_t)(bn + r) * K + cg * 8;
        blp[i] = BLO + (size_t)(bn + r) * K + cg * 8;
        aoff[i] = (uint32_t)(r * HSTR + cg * 4) * 4;
        boff[i] = (uint32_t)(HTILE + r * HSTR + cg * 4) * 4;
    }

    // layout per stage: [Ahi | Bhi | Alo | Blo]
#pragma unroll
    for (int i = 0; i < 2; i++) {
        cpa16(smb + aoff[i], ahp[i]);
        cpa16(smb + boff[i], bhp[i]);
        cpa16(smb + 2 * HTILE * 4 + aoff[i], alp[i]);
        cpa16(smb + 2 * HTILE * 4 + boff[i], blp[i]);
    }
    CP_COMMIT();

    float acc1[2][8][4], acc2[2][8][4];
#pragma unroll
    for (int mt = 0; mt < 2; mt++)
#pragma unroll
        for (int nt = 0; nt < 8; nt++)
#pragma unroll
            for (int q = 0; q < 4; q++) { acc1[mt][nt][q] = 0.f; acc2[mt][nt][q] = 0.f; }

    const int abase = (wm * 32 + g) * HSTR + tig;
    const int bbase = (wn * 64 + g) * HSTR + tig;
    const int KC = K / 32;

    for (int c = 0; c < KC; c++) {
        int s = c & 1;
        bool more = (c + 1 < KC);
        if (more) {
            uint32_t nb = smb + (uint32_t)(s ^ 1) * HCSTG * 4;
#pragma unroll
            for (int i = 0; i < 2; i++) {
                cpa16(nb + aoff[i], ahp[i] + (c + 1) * 32);
                cpa16(nb + boff[i], bhp[i] + (c + 1) * 32);
                cpa16(nb + 2 * HTILE * 4 + aoff[i], alp[i] + (c + 1) * 32);
                cpa16(nb + 2 * HTILE * 4 + boff[i], blp[i] + (c + 1) * 32);
            }
            CP_COMMIT();
            CP_WAIT1();
        } else {
            CP_WAIT0();
        }
        __syncthreads();

        const uint32_t* AH = SM + s * HCSTG;
        const uint32_t* BH = AH + HTILE;
        const uint32_t* AL = AH + 2 * HTILE;
        const uint32_t* BL = AH + 3 * HTILE;

#pragma unroll
        for (int ks = 0; ks < 2; ks++) {
            uint32_t ah[2][4], al[2][4];
#pragma unroll
            for (int mt = 0; mt < 2; mt++) {
                int a0 = abase + mt * 16 * HSTR + ks * 8;
                ah[mt][0] = AH[a0];            ah[mt][1] = AH[a0 + 8 * HSTR];
                ah[mt][2] = AH[a0 + 4];        ah[mt][3] = AH[a0 + 8 * HSTR + 4];
                al[mt][0] = AL[a0];            al[mt][1] = AL[a0 + 8 * HSTR];
                al[mt][2] = AL[a0 + 4];        al[mt][3] = AL[a0 + 8 * HSTR + 4];
            }
#pragma unroll
            for (int nt = 0; nt < 8; nt++) {
                int b0i = bbase + nt * 8 * HSTR + ks * 8;
                uint32_t b0 = BH[b0i], b1 = BH[b0i + 4];
                uint32_t c0 = BL[b0i], c1 = BL[b0i + 4];
#pragma unroll
                for (int mt = 0; mt < 2; mt++) {
                    MMA_F16(acc1[mt][nt], ah[mt], b0, b1);
                    MMA_F16(acc2[mt][nt], ah[mt], c0, c1);
                    MMA_F16(acc2[mt][nt], al[mt], b0, b1);
                }
            }
        }
        __syncthreads();
    }

#pragma unroll
    for (int mt = 0; mt < 2; mt++) {
        int mloc0 = wm * 32 + mt * 16 + g;
#pragma unroll
        for (int nt = 0; nt < 8; nt++) {
            int col = bn + wn * 64 + nt * 8 + 2 * tig;
            float* d1 = acc1[mt][nt];
            float* d2 = acc2[mt][nt];
            size_t i0 = (size_t)(bm + mloc0) * N + col;
            size_t i1 = (size_t)(bm + mloc0 + 8) * N + col;
            float2 v0 = make_float2(d1[0] + d2[0] * INVLOSCALE, d1[1] + d2[1] * INVLOSCALE);
            float2 v1 = make_float2(d1[2] + d2[2] * INVLOSCALE, d1[3] + d2[3] * INVLOSCALE);
            if (Res) {
                float2 r0 = *(const float2*)&Res[i0];
                float2 r1 = *(const float2*)&Res[i1];
                v0.x += r0.x; v0.y += r0.y; v1.x += r1.x; v1.y += r1.y;
            }
            *(float2*)&C[i0] = v0;
            *(float2*)&C[i1] = v1;
        }
    }
}

// ---------------- warp-per-token rmsnorms ----------------
// rmsnorm -> fp16 hi/lo split (feeds gemm_hc QKV)
__global__ __launch_bounds__(256) void rmsnorm_split(
    const float* __restrict__ x, const float* __restrict__ w,
    __half* __restrict__ ohi, __half* __restrict__ olo)
{
    int warp = threadIdx.x >> 5, lane = threadIdx.x & 31;
    int t = blockIdx.x * 8 + warp;
    const float4* xr = (const float4*)(x + (size_t)t * HHD);
    const float4* wr = (const float4*)w;
    uint2* ohr = (uint2*)(ohi + (size_t)t * HHD);
    uint2* olr = (uint2*)(olo + (size_t)t * HHD);
    float ss = 0.f;
    float4 xv[16];
#pragma unroll
    for (int it = 0; it < 16; it++) {
        xv[it] = xr[it * 32 + lane];
        ss += xv[it].x * xv[it].x + xv[it].y * xv[it].y
            + xv[it].z * xv[it].z + xv[it].w * xv[it].w;
    }
#pragma unroll
    for (int off = 16; off; off >>= 1) ss += __shfl_xor_sync(~0u, ss, off);
    float scale = rsqrtf(ss / (float)HHD + EPSV);
#pragma unroll
    for (int it = 0; it < 16; it++) {
        float4 wv = wr[it * 32 + lane];
        float v0 = xv[it].x * scale * wv.x, v1 = xv[it].y * scale * wv.y;
        float v2 = xv[it].z * scale * wv.z, v3 = xv[it].w * scale * wv.w;
        float h0 = __half2float(__float2half_rn(v0));
        float h1 = __half2float(__float2half_rn(v1));
        float h2 = __half2float(__float2half_rn(v2));
        float h3 = __half2float(__float2half_rn(v3));
        uint2 vh, vl;
        vh.x = packh2(v0, v1); vh.y = packh2(v2, v3);
        vl.x = packh2((v0 - h0) * LOSCALE, (v1 - h1) * LOSCALE);
        vl.y = packh2((v2 - h2) * LOSCALE, (v3 - h3) * LOSCALE);
        ohr[it * 32 + lane] = vh;
        olr[it * 32 + lane] = vl;
    }
}

// rmsnorm -> fp32 (router) + fp16 (GEMM A)
__global__ __launch_bounds__(256) void rmsnorm_dual(
    const float* __restrict__ x, const float* __restrict__ w,
    float* __restrict__ o32, __half* __restrict__ o16)
{
    int warp = threadIdx.x >> 5, lane = threadIdx.x & 31;
    int t = blockIdx.x * 8 + warp;
    const float4* xr = (const float4*)(x + (size_t)t * HHD);
    const float4* wr = (const float4*)w;
    float4* o32r = (float4*)(o32 + (size_t)t * HHD);
    uint2* o16r = (uint2*)(o16 + (size_t)t * HHD);
    float ss = 0.f;
    float4 xv[16];
#pragma unroll
    for (int it = 0; it < 16; it++) {
        xv[it] = xr[it * 32 + lane];
        ss += xv[it].x * xv[it].x + xv[it].y * xv[it].y
            + xv[it].z * xv[it].z + xv[it].w * xv[it].w;
    }
#pragma unroll
    for (int off = 16; off; off >>= 1) ss += __shfl_xor_sync(~0u, ss, off);
    float scale = rsqrtf(ss / (float)HHD + EPSV);
#pragma unroll
    for (int it = 0; it < 16; it++) {
        float4 wv = wr[it * 32 + lane];
        float4 v = make_float4(xv[it].x * scale * wv.x, xv[it].y * scale * wv.y,
                               xv[it].z * scale * wv.z, xv[it].w * scale * wv.w);
        o32r[it * 32 + lane] = v;
        uint2 hh;
        hh.x = packh2(v.x, v.y);
        hh.y = packh2(v.z, v.w);
        o16r[it * 32 + lane] = hh;
    }
}

// ---------------- rope + q/k rmsnorm ----------------
__global__ __launch_bounds__(256) void ropenorm_kernel(
    float* __restrict__ qkv, const int* __restrict__ pos,
    const float* __restrict__ qw, const float* __restrict__ kw)
{
    int t = blockIdx.x, tid = threadIdx.x;
    float* row = qkv + (size_t)t * QKVN;
    float p = (float)pos[t];
    const float lgt = logf(500000.0f);
    __shared__ float red[256];
    __shared__ float sq, sk;

    float ss = 0.f;
    for (int idx = tid; idx < 1024; idx += 256) {
        int hh = idx >> 6, i = idx & 63;
        float inv = expf(-lgt * (float)i * (1.0f / 64.0f));
        float fr = p * inv, c = cosf(fr), s = sinf(fr);
        float x1 = row[hh * 128 + i], x2 = row[hh * 128 + 64 + i];
        float o1 = x1 * c - x2 * s, o2 = x2 * c + x1 * s;
        row[hh * 128 + i] = o1; row[hh * 128 + 64 + i] = o2;
        ss += o1 * o1 + o2 * o2;
    }
    red[tid] = ss; __syncthreads();
    for (int s2 = 128; s2 > 0; s2 >>= 1) { if (tid < s2) red[tid] += red[tid + s2]; __syncthreads(); }
    if (tid == 0) sq = rsqrtf(red[0] / (float)QSZ + EPSV);
    __syncthreads();

    float ssk = 0.f;
    {
        int hh = tid >> 6, i = tid & 63;
        float inv = expf(-lgt * (float)i * (1.0f / 64.0f));
        float fr = p * inv, c = cosf(fr), s = sinf(fr);
        float* kb = row + QSZ;
        float x1 = kb[hh * 128 + i], x2 = kb[hh * 128 + 64 + i];
        float o1 = x1 * c - x2 * s, o2 = x2 * c + x1 * s;
        kb[hh * 128 + i] = o1; kb[hh * 128 + 64 + i] = o2;
        ssk = o1 * o1 + o2 * o2;
    }
    red[tid] = ssk; __syncthreads();
    for (int s2 = 128; s2 > 0; s2 >>= 1) { if (tid < s2) red[tid] += red[tid + s2]; __syncthreads(); }
    if (tid == 0) sk = rsqrtf(red[0] / (float)KVSZ + EPSV);
    __syncthreads();

    for (int j = tid; j < QSZ; j += 256) row[j] *= sq * qw[j];
    for (int j = tid; j < KVSZ; j += 256) row[QSZ + j] *= sk * kw[j];
}

// ---------------- flash attention (fp32, BM=64) with hi/lo fp16 output ----------------
#define QKSTR 132
#define PSTR  68
#define SMEM_ATTN ((3 * 64 * QKSTR + 64 * PSTR) * 4)

__global__ __launch_bounds__(256) void attn_kernel(
    const float* __restrict__ qkv, __half* __restrict__ Ohi, __half* __restrict__ Olo)
{
    extern __shared__ float sh[];
    float* Qs = sh;
    float* Ks = sh + 64 * QKSTR;
    float* Vs = sh + 2 * 64 * QKSTR;
    float* Ps = sh + 3 * 64 * QKSTR;

    int m0 = ((int)gridDim.x - 1 - (int)blockIdx.x) * 64;
    int h  = blockIdx.y;
    int kvh = h >> 2;
    int tid = threadIdx.x, lane = tid & 31, w = tid >> 5;
    const float scl = 0.08838834764831845f;

    for (int i = tid; i < 2048; i += 256) {
        int r = i >> 5, c = (i & 31) << 2;
        *(float4*)&Qs[r * QKSTR + c] =
            *(const float4*)&qkv[(size_t)(m0 + r) * QKVN + h * HDIM + c];
    }

    float mrow[8], lrow[8], oacc[8][4];
#pragma unroll
    for (int r = 0; r < 8; r++) {
        mrow[r] = -1e30f; lrow[r] = 0.f;
        oacc[r][0] = oacc[r][1] = oacc[r][2] = oacc[r][3] = 0.f;
    }
    int d0 = lane << 2;

    for (int n0 = 0; n0 <= m0; n0 += 64) {
        __syncthreads();
        for (int i = tid; i < 2048; i += 256) {
            int r = i >> 5, c = (i & 31) << 2;
            *(float4*)&Ks[r * QKSTR + c] =
                *(const float4*)&qkv[(size_t)(n0 + r) * QKVN + QSZ + kvh * HDIM + c];
            *(float4*)&Vs[r * QKSTR + c] =
                *(const float4*)&qkv[(size_t)(n0 + r) * QKVN + QSZ + KVSZ + kvh * HDIM + c];
        }
        __syncthreads();

        float s0[8] = {0,0,0,0,0,0,0,0};
        float s1[8] = {0,0,0,0,0,0,0,0};
#pragma unroll 4
        for (int k = 0; k < 128; k += 4) {
            float4 k0 = *(float4*)&Ks[lane * QKSTR + k];
            float4 k1 = *(float4*)&Ks[(lane + 32) * QKSTR + k];
#pragma unroll
            for (int r = 0; r < 8; r++) {
                float4 q = *(float4*)&Qs[(w * 8 + r) * QKSTR + k];
                s0[r] += q.x * k0.x + q.y * k0.y + q.z * k0.z + q.w * k0.w;
                s1[r] += q.x * k1.x + q.y * k1.y + q.z * k1.z + q.w * k1.w;
            }
        }
        bool diag = (n0 + 63 > m0);
#pragma unroll
        for (int r = 0; r < 8; r++) {
            int grow = m0 + w * 8 + r;
            float v0 = s0[r] * scl, v1 = s1[r] * scl;
            if (diag) {
                if (n0 + lane      > grow) v0 = -1e30f;
                if (n0 + lane + 32 > grow) v1 = -1e30f;
            }
            float tmax = fmaxf(v0, v1);
#pragma unroll
            for (int o = 16; o; o >>= 1) tmax = fmaxf(tmax, __shfl_xor_sync(~0u, tmax, o));
            float nm = fmaxf(mrow[r], tmax);
            float p0 = __expf(v0 - nm), p1 = __expf(v1 - nm);
            float corr = __expf(mrow[r] - nm);
            float psum = p0 + p1;
#pragma unroll
            for (int o = 16; o; o >>= 1) psum += __shfl_xor_sync(~0u, psum, o);
            lrow[r] = lrow[r] * corr + psum;
            mrow[r] = nm;
            oacc[r][0] *= corr; oacc[r][1] *= corr; oacc[r][2] *= corr; oacc[r][3] *= corr;
            Ps[(w * 8 + r) * PSTR + lane]      = p0;
            Ps[(w * 8 + r) * PSTR + lane + 32] = p1;
        }
        __syncwarp();
#pragma unroll 2
        for (int n = 0; n < 64; n += 4) {
            float4 v0 = *(float4*)&Vs[(n + 0) * QKSTR + d0];
            float4 v1 = *(float4*)&Vs[(n + 1) * QKSTR + d0];
            float4 v2 = *(float4*)&Vs[(n + 2) * QKSTR + d0];
            float4 v3 = *(float4*)&Vs[(n + 3) * QKSTR + d0];
#pragma unroll
            for (int r = 0; r < 8; r++) {
                float4 pv = *(float4*)&Ps[(w * 8 + r) * PSTR + n];
                oacc[r][0] += pv.x * v0.x + pv.y * v1.x + pv.z * v2.x + pv.w * v3.x;
                oacc[r][1] += pv.x * v0.y + pv.y * v1.y + pv.z * v2.y + pv.w * v3.y;
                oacc[r][2] += pv.x * v0.z + pv.y * v1.z + pv.z * v2.z + pv.w * v3.z;
                oacc[r][3] += pv.x * v0.w + pv.y * v1.w + pv.z * v2.w + pv.w * v3.w;
            }
        }
    }
#pragma unroll
    for (int r = 0; r < 8; r++) {
        float inv = 1.0f / lrow[r];
        float v0 = oacc[r][0] * inv, v1 = oacc[r][1] * inv;
        float v2 = oacc[r][2] * inv, v3 = oacc[r][3] * inv;
        float h0 = __half2float(__float2half_rn(v0));
        float h1 = __half2float(__float2half_rn(v1));
        float h2 = __half2float(__float2half_rn(v2));
        float h3 = __half2float(__float2half_rn(v3));
        uint2 vh, vl;
        vh.x = packh2(v0, v1); vh.y = packh2(v2, v3);
        vl.x = packh2((v0 - h0) * LOSCALE, (v1 - h1) * LOSCALE);
        vl.y = packh2((v2 - h2) * LOSCALE, (v3 - h3) * LOSCALE);
        size_t o = (size_t)(m0 + w * 8 + r) * QSZ + h * HDIM + d0;
        *(uint2*)&Ohi[o] = vh;
        *(uint2*)&Olo[o] = vl;
    }
}

// ---------------- router / permutation ----------------
__global__ void zero_kernel()
{
    int i = threadIdx.x;
    if (i < NEXP) { g_cnt[i] = 0; g_cur[i] = 0; }
}

__global__ __launch_bounds__(256) void router_kernel(
    const float* __restrict__ y, const float* __restrict__ rw)
{
    int warp = threadIdx.x >> 5, lane = threadIdx.x & 31;
    int t = blockIdx.x * 8 + warp;
    const float4* xr = (const float4*)(y + (size_t)t * HHD);
    float part[NEXP] = {};
#pragma unroll 4
    for (int it = 0; it < 16; it++) {
        int kq = it * 32 + lane;
        float4 xv = xr[kq];
        const float* r0 = rw + (size_t)(kq * 4) * NEXP;
#pragma unroll
        for (int e = 0; e < NEXP; e++)
            part[e] += xv.x * r0[e] + xv.y * r0[NEXP + e]
                     + xv.z * r0[2 * NEXP + e] + xv.w * r0[3 * NEXP + e];
    }
#pragma unroll
    for (int e = 0; e < NEXP; e++)
#pragma unroll
        for (int o = 16; o; o >>= 1) part[e] += __shfl_xor_sync(~0u, part[e], o);
    if (lane == 0) {
        int am = 0; float mv = part[0];
#pragma unroll
        for (int e = 1; e < NEXP; e++) if (part[e] > mv) { mv = part[e]; am = e; }
        g_expert[t] = am;
        g_gate[t]   = 1.0f / (1.0f + expf(-mv));
        atomicAdd(&g_cnt[am], 1);
    }
}

__global__ void scan_kernel()
{
    int s = 0;
    for (int e = 0; e < NEXP; e++) { g_off[e] = s; s += g_cnt[e]; }
}

__global__ void scatter_kernel()
{
    int t = blockIdx.x * 256 + threadIdx.x;
    if (t >= TT) return;
    int e = g_expert[t];
    int p = atomicAdd(&g_cur[e], 1);
    g_perm[g_off[e] + p] = t;
}

// ---------------- launcher ----------------
extern "C" void kernel_launch(void* const* d_in, const int* in_sizes, int n_in,
                              void* d_out, int out_size)
{
    const int*   positions = (const int*)  d_in[0];
    const float* hidden    = (const float*)d_in[1];
    const float* ln1       = (const float*)d_in[2];
    const float* ln2       = (const float*)d_in[3];
    const float* w_qkv     = (const float*)d_in[4];
    const float* w_o       = (const float*)d_in[5];
    const float* qnw       = (const float*)d_in[6];
    const float* knw       = (const float*)d_in[7];
    const float* rw        = (const float*)d_in[8];
    const float* wsg       = (const float*)d_in[9];
    const float* wsu       = (const float*)d_in[10];
    const float* wsd       = (const float*)d_in[11];
    const float* weg       = (const float*)d_in[12];
    const float* weu       = (const float*)d_in[13];
    const float* wed       = (const float*)d_in[14];
    float* out = (float*)d_out;

    void* p;
    cudaGetSymbolAddress(&p, g_xn);
    __half* xhi = (__half*)p;
    __half* xlo = (__half*)((float*)p + TT * HHD / 2);
    cudaGetSymbolAddress(&p, g_qkv); float* qkv = (float*)p;
    cudaGetSymbolAddress(&p, g_att);
    __half* atthi = (__half*)p;
    __half* attlo = (__half*)((float*)p + TT * QSZ / 2);
    cudaGetSymbolAddress(&p, g_x2);  float* x2  = (float*)p;
    cudaGetSymbolAddress(&p, g_y);   float* y   = (float*)p;
    cudaGetSymbolAddress(&p, g_y16); __half* y16 = (__half*)p;
    cudaGetSymbolAddress(&p, g_g);   __half* gg16 = (__half*)p;
    cudaGetSymbolAddress(&p, g_wqkvT);  __half* wqkvT  = (__half*)p;
    cudaGetSymbolAddress(&p, g_wqkvTl); __half* wqkvTl = (__half*)p;
    cudaGetSymbolAddress(&p, g_woT);    __half* woT    = (__half*)p;
    cudaGetSymbolAddress(&p, g_woTl);   __half* woTl   = (__half*)p;
    cudaGetSymbolAddress(&p, g_wsgT);   __half* wsgT   = (__half*)p;
    cudaGetSymbolAddress(&p, g_wsuT);   __half* wsuT   = (__half*)p;
    cudaGetSymbolAddress(&p, g_wsdT);   __half* wsdT   = (__half*)p;
    cudaGetSymbolAddress(&p, g_wegT);   __half* wegT   = (__half*)p;
    cudaGetSymbolAddress(&p, g_weuT);   __half* weuT   = (__half*)p;
    cudaGetSymbolAddress(&p, g_wedT);   __half* wedT   = (__half*)p;

    cudaFuncSetAttribute(attn_kernel, cudaFuncAttributeMaxDynamicSharedMemorySize, SMEM_ATTN);
    cudaFuncSetAttribute(gemm_hc, cudaFuncAttributeMaxDynamicSharedMemorySize, SMEM_HC);
    cudaFuncSetAttribute(gemm_h<0>, cudaFuncAttributeMaxDynamicSharedMemorySize, SMEM_H);
    cudaFuncSetAttribute(gemm_h<2>, cudaFuncAttributeMaxDynamicSharedMemorySize, SMEM_H);
    cudaFuncSetAttribute(gemm_gu<0>, cudaFuncAttributeMaxDynamicSharedMemorySize, SMEM_GU);
    cudaFuncSetAttribute(gemm_gu<1>, cudaFuncAttributeMaxDynamicSharedMemorySize, SMEM_GU);

    // weight prep
    transpose_split_h<<<dim3(QKVN / 64, HHD / 64), 256>>>(w_qkv, wqkvT, wqkvTl, HHD, QKVN);
    transpose_split_h<<<dim3(HHD / 64, QSZ / 64), 256>>>(w_o, woT, woTl, QSZ, HHD);
    transpose_f16<<<dim3(II / 64, HHD / 64), 256>>>(wsg, wsgT, HHD, II);
    transpose_f16<<<dim3(II / 64, HHD / 64), 256>>>(wsu, wsuT, HHD, II);
    transpose_f16<<<dim3(HHD / 64, II / 64), 256>>>(wsd, wsdT, II, HHD);
    transpose_f16<<<dim3(II / 64, HHD / 64, NEXP), 256>>>(weg, wegT, HHD, II);
    transpose_f16<<<dim3(II / 64, HHD / 64, NEXP), 256>>>(weu, weuT, HHD, II);
    transpose_f16<<<dim3(HHD / 64, II / 64, NEXP), 256>>>(wed, wedT, II, HHD);

    // 1. x = rmsnorm(hidden, ln1) -> fp16 hi/lo (feeds QKV gemm_hc only)
    rmsnorm_split<<<TT / 8, 256>>>(hidden, ln1, xhi, xlo);
    // 2. qkv = x @ w_qkv   (double-fp16 compensated, all-cp.async)
    gemm_hc<<<dim3(QKVN / 128, TT / 128), 256, SMEM_HC>>>(xhi, xlo, wqkvT, wqkvTl, qkv, TT, QKVN, HHD, nullptr);
    // 3. rope + q/k norm
    ropenorm_kernel<<<TT, 256>>>(qkv, positions, qnw, knw);
    // 4. attention (BM=64), epilogue emits hi/lo fp16
    attn_kernel<<<dim3(TT / 64, NHEADS), 256, SMEM_ATTN>>>(qkv, atthi, attlo);
    // 5. x2 = hidden + attn @ w_o   (compensated, all-cp.async)
    gemm_hc<<<dim3(HHD / 128, TT / 128), 256, SMEM_HC>>>(atthi, attlo, woT, woTl, x2, TT, HHD, QSZ, hidden);
    // 6. y = rmsnorm(x2, ln2)  -> fp32 (router) + fp16 (GEMM A)
    rmsnorm_dual<<<TT / 8, 256>>>(x2, ln2, y, y16);
    // 7. router (fp32, warp-per-token)
    zero_kernel<<<1, 32>>>();
    router_kernel<<<TT / 8, 256>>>(y, rw);
    scan_kernel<<<1, 1>>>();
    scatter_kernel<<<TT / 256, 256>>>();
    // 8. shared expert: fused gate+up+silu (fp16 out), then down (+x2 residual)
    gemm_gu<0><<<dim3(II / 128, TT / 128), 256, SMEM_GU>>>(y16, wsgT, wsuT, gg16, TT, II, HHD);
    gemm_h<0><<<dim3(HHD / 128, TT / 128), 256, SMEM_H>>>(gg16, wsdT, out, TT, HHD, II, x2);
    // 9. routed experts: fused grouped gate+up+silu, then grouped scatter-add down
    gemm_gu<1><<<dim3(II / 128, TT / 128, NEXP), 256, SMEM_GU>>>(y16, wegT, weuT, gg16, TT, II, HHD);
    gemm_h<2><<<dim3(HHD / 128, TT / 128, NEXP), 256, SMEM_H>>>(gg16, wedT, out, TT, HHD, II, nullptr);
}